// round 3
// baseline (speedup 1.0000x reference)
#include <cuda_runtime.h>
#include <cuda_bf16.h>
#include <cstdint>

// Problem constants (fixed by dataset)
#define NMAX   20000
#define EMAX   320000
#define DIN    512
#define DH     256
#define NGR    128

// ---------------- scratch (static device globals; no runtime alloc) ----------
__device__ int   g_deg[NMAX];
__device__ int   g_rowstart[NMAX + 1];
__device__ int   g_cursor[NMAX];
__device__ int   g_csr[EMAX];
__device__ float g_dinv[NMAX];
__device__ float g_y[(size_t)NMAX * DH];   // gemm output (pre-aggregate), reused for layer 2
__device__ float g_h[(size_t)NMAX * DH];   // layer-1 hidden
__device__ float g_gsum[NGR];
__device__ int   g_cnt[NGR];

// ---------------- small utility kernels --------------------------------------
__global__ void zero_kernel(int n) {
    int i = blockIdx.x * blockDim.x + threadIdx.x;
    if (i < n) g_deg[i] = 0;
    if (i < NGR) { g_gsum[i] = 0.0f; g_cnt[i] = 0; }
}

// histogram of in-degrees (dst row of edge_index) + per-graph node counts
__global__ void hist_kernel(const int* __restrict__ ei, const int* __restrict__ batch,
                            int n, int e) {
    int i = blockIdx.x * blockDim.x + threadIdx.x;
    if (i < e) atomicAdd(&g_deg[ei[e + i]], 1);
    if (i < n) atomicAdd(&g_cnt[batch[i]], 1);
}

// single-block exclusive scan of g_deg -> g_rowstart / g_cursor, plus dinv
__global__ void scan_kernel(int n) {
    __shared__ int wsum[32];
    int tid = threadIdx.x;
    int lane = tid & 31, wid = tid >> 5;
    int run = 0;
    int nchunks = (n + 1023) / 1024;
    for (int c = 0; c < nchunks; ++c) {
        int i = c * 1024 + tid;
        int v = (i < n) ? g_deg[i] : 0;
        // warp inclusive scan
        int x = v;
        #pragma unroll
        for (int off = 1; off < 32; off <<= 1) {
            int t = __shfl_up_sync(0xffffffffu, x, off);
            if (lane >= off) x += t;
        }
        if (lane == 31) wsum[wid] = x;
        __syncthreads();
        if (wid == 0) {
            int s = wsum[lane];
            #pragma unroll
            for (int off = 1; off < 32; off <<= 1) {
                int t = __shfl_up_sync(0xffffffffu, s, off);
                if (lane >= off) s += t;
            }
            wsum[lane] = s;
        }
        __syncthreads();
        int woff = (wid > 0) ? wsum[wid - 1] : 0;
        int incl = x + woff;
        int total = wsum[31];
        if (i < n) {
            int excl = run + incl - v;
            g_rowstart[i] = excl;
            g_cursor[i]   = excl;
            g_dinv[i]     = rsqrtf((float)(v + 1));   // +1 self-loop
        }
        run += total;
        __syncthreads();
    }
    if (tid == 0) g_rowstart[n] = run;
}

__global__ void fill_kernel(const int* __restrict__ ei, int e) {
    int i = blockIdx.x * blockDim.x + threadIdx.x;
    if (i < e) {
        int s = ei[i];
        int d = ei[e + i];
        int p = atomicAdd(&g_cursor[d], 1);
        g_csr[p] = s;
    }
}

// ---------------- tf32 tensor-core GEMM:  Y[m,:] = scale[m] * (A[m,:] @ B) ----
__device__ __forceinline__ uint32_t f2tf(float f) {
    uint32_t r;
    asm("cvt.rna.tf32.f32 %0, %1;" : "=r"(r) : "f"(f));
    return r;
}

__device__ __forceinline__ void mma_tf32(float* c, const uint32_t* a, const uint32_t* b) {
    asm volatile(
        "mma.sync.aligned.m16n8k8.row.col.f32.tf32.tf32.f32 "
        "{%0,%1,%2,%3}, {%4,%5,%6,%7}, {%8,%9}, {%0,%1,%2,%3};\n"
        : "+f"(c[0]), "+f"(c[1]), "+f"(c[2]), "+f"(c[3])
        : "r"(a[0]), "r"(a[1]), "r"(a[2]), "r"(a[3]),
          "r"(b[0]), "r"(b[1]));
}

#define BM 128
#define BN 64
#define BKT 32
// 256 threads = 8 warps in a 4(M) x 2(N) grid, each warp computes 32x32.
__global__ __launch_bounds__(256)
void gemm_tf32_scaled(const float* __restrict__ A, const float* __restrict__ B,
                      const float* __restrict__ scale, float* __restrict__ Y,
                      int M, int K) {
    __shared__ uint32_t As[BM][36];  // padded: 4*gid+tig -> conflict-free frag loads
    __shared__ uint32_t Bs[BKT][72]; // padded: 8*tig+gid -> conflict-free frag loads

    int tid  = threadIdx.x;
    int lane = tid & 31, warp = tid >> 5;
    int wm = warp >> 1, wn = warp & 1;
    int gid = lane >> 2, tig = lane & 3;
    int m0 = blockIdx.x * BM;
    int n0 = blockIdx.y * BN;

    float c[2][4][4] = {};

    for (int k0 = 0; k0 < K; k0 += BKT) {
        // A tile: 128x32 floats = 1024 float4, 4 per thread
        #pragma unroll
        for (int t = 0; t < 4; ++t) {
            int f4 = tid + t * 256;
            int r = f4 >> 3, cc = (f4 & 7) << 2;
            int gr = m0 + r;
            float4 v = make_float4(0.f, 0.f, 0.f, 0.f);
            if (gr < M) v = *(const float4*)(A + (size_t)gr * K + k0 + cc);
            As[r][cc + 0] = f2tf(v.x);
            As[r][cc + 1] = f2tf(v.y);
            As[r][cc + 2] = f2tf(v.z);
            As[r][cc + 3] = f2tf(v.w);
        }
        // B tile: 32x64 floats = 512 float4, 2 per thread
        #pragma unroll
        for (int t = 0; t < 2; ++t) {
            int f4 = tid + t * 256;
            int r = f4 >> 4, cc = (f4 & 15) << 2;
            float4 v = *(const float4*)(B + (size_t)(k0 + r) * DH + n0 + cc);
            Bs[r][cc + 0] = f2tf(v.x);
            Bs[r][cc + 1] = f2tf(v.y);
            Bs[r][cc + 2] = f2tf(v.z);
            Bs[r][cc + 3] = f2tf(v.w);
        }
        __syncthreads();

        #pragma unroll
        for (int kk = 0; kk < BKT; kk += 8) {
            uint32_t a[2][4], b[4][2];
            #pragma unroll
            for (int i = 0; i < 2; ++i) {
                int mrow = wm * 32 + i * 16;
                a[i][0] = As[mrow + gid][kk + tig];
                a[i][1] = As[mrow + gid + 8][kk + tig];
                a[i][2] = As[mrow + gid][kk + tig + 4];
                a[i][3] = As[mrow + gid + 8][kk + tig + 4];
            }
            #pragma unroll
            for (int j = 0; j < 4; ++j) {
                int ncol = wn * 32 + j * 8 + gid;
                b[j][0] = Bs[kk + tig][ncol];
                b[j][1] = Bs[kk + tig + 4][ncol];
            }
            #pragma unroll
            for (int i = 0; i < 2; ++i)
                #pragma unroll
                for (int j = 0; j < 4; ++j)
                    mma_tf32(c[i][j], a[i], b[j]);
        }
        __syncthreads();
    }

    // epilogue: scale rows by dinv[m]
    #pragma unroll
    for (int i = 0; i < 2; ++i) {
        int r0 = m0 + wm * 32 + i * 16 + gid;
        int r1 = r0 + 8;
        float s0 = (r0 < M) ? scale[r0] : 0.f;
        float s1 = (r1 < M) ? scale[r1] : 0.f;
        #pragma unroll
        for (int j = 0; j < 4; ++j) {
            int cb = n0 + wn * 32 + j * 8 + tig * 2;
            if (r0 < M) {
                Y[(size_t)r0 * DH + cb]     = s0 * c[i][j][0];
                Y[(size_t)r0 * DH + cb + 1] = s0 * c[i][j][1];
            }
            if (r1 < M) {
                Y[(size_t)r1 * DH + cb]     = s1 * c[i][j][2];
                Y[(size_t)r1 * DH + cb + 1] = s1 * c[i][j][3];
            }
        }
    }
}

// ---------------- warp-per-node gather aggregation ----------------------------
// out[node,:] = relu( dinv[node] * (sum_{src in in(node)} y[src,:] + y[node,:]) + bias )
__global__ __launch_bounds__(256)
void aggregate1_kernel(const float* __restrict__ y, const float* __restrict__ bias,
                       float* __restrict__ out, int n) {
    int gw   = (blockIdx.x * blockDim.x + threadIdx.x) >> 5;
    int lane = threadIdx.x & 31;
    if (gw >= n) return;
    int e0 = g_rowstart[gw], e1 = g_rowstart[gw + 1];

    float4 a0 = make_float4(0.f, 0.f, 0.f, 0.f);
    float4 a1 = make_float4(0.f, 0.f, 0.f, 0.f);

    int e = e0;
    for (; e + 4 <= e1; e += 4) {
        int s0 = g_csr[e], s1 = g_csr[e + 1], s2 = g_csr[e + 2], s3 = g_csr[e + 3];
        const float4* p0 = (const float4*)(y + (size_t)s0 * DH) + lane;
        const float4* p1 = (const float4*)(y + (size_t)s1 * DH) + lane;
        const float4* p2 = (const float4*)(y + (size_t)s2 * DH) + lane;
        const float4* p3 = (const float4*)(y + (size_t)s3 * DH) + lane;
        float4 u0 = p0[0], w0 = p0[32];
        float4 u1 = p1[0], w1 = p1[32];
        float4 u2 = p2[0], w2 = p2[32];
        float4 u3 = p3[0], w3 = p3[32];
        a0.x += u0.x + u1.x + u2.x + u3.x;  a0.y += u0.y + u1.y + u2.y + u3.y;
        a0.z += u0.z + u1.z + u2.z + u3.z;  a0.w += u0.w + u1.w + u2.w + u3.w;
        a1.x += w0.x + w1.x + w2.x + w3.x;  a1.y += w0.y + w1.y + w2.y + w3.y;
        a1.z += w0.z + w1.z + w2.z + w3.z;  a1.w += w0.w + w1.w + w2.w + w3.w;
    }
    for (; e < e1; ++e) {
        int s = g_csr[e];
        const float4* p = (const float4*)(y + (size_t)s * DH) + lane;
        float4 u = p[0], w = p[32];
        a0.x += u.x; a0.y += u.y; a0.z += u.z; a0.w += u.w;
        a1.x += w.x; a1.y += w.y; a1.z += w.z; a1.w += w.w;
    }
    // self loop
    {
        const float4* p = (const float4*)(y + (size_t)gw * DH) + lane;
        float4 u = p[0], w = p[32];
        a0.x += u.x; a0.y += u.y; a0.z += u.z; a0.w += u.w;
        a1.x += w.x; a1.y += w.y; a1.z += w.z; a1.w += w.w;
    }
    float dv = g_dinv[gw];
    float4 b0 = ((const float4*)bias)[lane];
    float4 b1 = ((const float4*)bias)[32 + lane];
    float4 r0, r1;
    r0.x = fmaxf(dv * a0.x + b0.x, 0.f); r0.y = fmaxf(dv * a0.y + b0.y, 0.f);
    r0.z = fmaxf(dv * a0.z + b0.z, 0.f); r0.w = fmaxf(dv * a0.w + b0.w, 0.f);
    r1.x = fmaxf(dv * a1.x + b1.x, 0.f); r1.y = fmaxf(dv * a1.y + b1.y, 0.f);
    r1.z = fmaxf(dv * a1.z + b1.z, 0.f); r1.w = fmaxf(dv * a1.w + b1.w, 0.f);
    float4* op = (float4*)(out + (size_t)gw * DH) + lane;
    op[0]  = r0;
    op[32] = r1;
}

// layer-2 aggregate fused with pool+FC: never materializes h2.
__global__ __launch_bounds__(256)
void aggregate2_pool_kernel(const float* __restrict__ y, const float* __restrict__ bias,
                            const float* __restrict__ wfc, const int* __restrict__ batch,
                            int n) {
    int gw   = (blockIdx.x * blockDim.x + threadIdx.x) >> 5;
    int lane = threadIdx.x & 31;
    if (gw >= n) return;
    int e0 = g_rowstart[gw], e1 = g_rowstart[gw + 1];

    float4 a0 = make_float4(0.f, 0.f, 0.f, 0.f);
    float4 a1 = make_float4(0.f, 0.f, 0.f, 0.f);

    int e = e0;
    for (; e + 4 <= e1; e += 4) {
        int s0 = g_csr[e], s1 = g_csr[e + 1], s2 = g_csr[e + 2], s3 = g_csr[e + 3];
        const float4* p0 = (const float4*)(y + (size_t)s0 * DH) + lane;
        const float4* p1 = (const float4*)(y + (size_t)s1 * DH) + lane;
        const float4* p2 = (const float4*)(y + (size_t)s2 * DH) + lane;
        const float4* p3 = (const float4*)(y + (size_t)s3 * DH) + lane;
        float4 u0 = p0[0], w0 = p0[32];
        float4 u1 = p1[0], w1 = p1[32];
        float4 u2 = p2[0], w2 = p2[32];
        float4 u3 = p3[0], w3 = p3[32];
        a0.x += u0.x + u1.x + u2.x + u3.x;  a0.y += u0.y + u1.y + u2.y + u3.y;
        a0.z += u0.z + u1.z + u2.z + u3.z;  a0.w += u0.w + u1.w + u2.w + u3.w;
        a1.x += w0.x + w1.x + w2.x + w3.x;  a1.y += w0.y + w1.y + w2.y + w3.y;
        a1.z += w0.z + w1.z + w2.z + w3.z;  a1.w += w0.w + w1.w + w2.w + w3.w;
    }
    for (; e < e1; ++e) {
        int s = g_csr[e];
        const float4* p = (const float4*)(y + (size_t)s * DH) + lane;
        float4 u = p[0], w = p[32];
        a0.x += u.x; a0.y += u.y; a0.z += u.z; a0.w += u.w;
        a1.x += w.x; a1.y += w.y; a1.z += w.z; a1.w += w.w;
    }
    {
        const float4* p = (const float4*)(y + (size_t)gw * DH) + lane;
        float4 u = p[0], w = p[32];
        a0.x += u.x; a0.y += u.y; a0.z += u.z; a0.w += u.w;
        a1.x += w.x; a1.y += w.y; a1.z += w.z; a1.w += w.w;
    }
    float dv = g_dinv[gw];
    float4 b0 = ((const float4*)bias)[lane];
    float4 b1 = ((const float4*)bias)[32 + lane];
    float4 f0 = ((const float4*)wfc)[lane];
    float4 f1 = ((const float4*)wfc)[32 + lane];

    float h;
    float dot = 0.f;
    h = fmaxf(dv * a0.x + b0.x, 0.f); dot += h * f0.x;
    h = fmaxf(dv * a0.y + b0.y, 0.f); dot += h * f0.y;
    h = fmaxf(dv * a0.z + b0.z, 0.f); dot += h * f0.z;
    h = fmaxf(dv * a0.w + b0.w, 0.f); dot += h * f0.w;
    h = fmaxf(dv * a1.x + b1.x, 0.f); dot += h * f1.x;
    h = fmaxf(dv * a1.y + b1.y, 0.f); dot += h * f1.y;
    h = fmaxf(dv * a1.z + b1.z, 0.f); dot += h * f1.z;
    h = fmaxf(dv * a1.w + b1.w, 0.f); dot += h * f1.w;

    #pragma unroll
    for (int off = 16; off > 0; off >>= 1)
        dot += __shfl_xor_sync(0xffffffffu, dot, off);
    if (lane == 0)
        atomicAdd(&g_gsum[batch[gw]], dot);
}

__global__ void finalize_kernel(float* __restrict__ out, const float* __restrict__ bfc) {
    int g = threadIdx.x;
    if (g < NGR)
        out[g] = g_gsum[g] / fmaxf((float)g_cnt[g], 1.0f) + bfc[0];
}

// ---------------- launch ------------------------------------------------------
extern "C" void kernel_launch(void* const* d_in, const int* in_sizes, int n_in,
                              void* d_out, int out_size) {
    const float* x     = (const float*)d_in[0];
    const int*   ei    = (const int*)  d_in[1];
    const int*   batch = (const int*)  d_in[2];
    const float* W1    = (const float*)d_in[3];
    const float* b1    = (const float*)d_in[4];
    const float* W2    = (const float*)d_in[5];
    const float* b2    = (const float*)d_in[6];
    const float* wfc   = (const float*)d_in[7];
    const float* bfc   = (const float*)d_in[8];
    float* out = (float*)d_out;

    int n = in_sizes[0] / DIN;   // 20000
    int e = in_sizes[1] / 2;     // 320000

    float* yptr = nullptr;
    float* hptr = nullptr;
    cudaGetSymbolAddress((void**)&yptr, g_y);
    cudaGetSymbolAddress((void**)&hptr, g_h);

    int tz = (n + 255) / 256;
    zero_kernel<<<tz, 256>>>(n);

    int th = (e + 255) / 256;
    hist_kernel<<<th, 256>>>(ei, batch, n, e);

    scan_kernel<<<1, 1024>>>(n);

    fill_kernel<<<th, 256>>>(ei, e);

    float* dinvptr = nullptr;
    cudaGetSymbolAddress((void**)&dinvptr, g_dinv);

    dim3 ggrid((n + BM - 1) / BM, DH / BN);
    gemm_tf32_scaled<<<ggrid, 256>>>(x, W1, dinvptr, yptr, n, DIN);

    int ta = ((n * 32) + 255) / 256;
    aggregate1_kernel<<<ta, 256>>>(yptr, b1, hptr, n);

    gemm_tf32_scaled<<<ggrid, 256>>>(hptr, W2, dinvptr, yptr, n, DH);

    aggregate2_pool_kernel<<<ta, 256>>>(yptr, b2, wfc, batch, n);

    finalize_kernel<<<1, NGR>>>(out, bfc);
}

// round 4
// speedup vs baseline: 1.0666x; 1.0666x over previous
#include <cuda_runtime.h>
#include <cuda_bf16.h>
#include <cstdint>

// Problem constants (fixed by dataset)
#define NMAX   20000
#define EMAX   320000
#define DIN    512
#define DH     256
#define NGR    128
#define NCSR   64                      // CSR-builder blocks inside hybrid kernel
#define CSR_THREADS (NCSR * 256)

// ---------------- scratch (static device globals; no runtime alloc) ----------
__device__ int   g_deg[NMAX];
__device__ int   g_rowstart[NMAX + 1];
__device__ int   g_cursor[NMAX];
__device__ int   g_csr[EMAX];
__device__ float g_dinv[NMAX];
__device__ float g_y[(size_t)NMAX * DH];
__device__ float g_h[(size_t)NMAX * DH];
__device__ float g_gsum[NGR];
__device__ int   g_cnt[NGR];
__device__ int   g_blocksum[NCSR];
__device__ volatile unsigned g_bar[4];

// ---------------- reset (must run before each hybrid launch) ------------------
__global__ void reset_bar_kernel() {
    if (threadIdx.x < 4) g_bar[threadIdx.x] = 0u;
}

// ---------------- spin barrier among the NCSR builder blocks ------------------
__device__ __forceinline__ void csr_barrier(int id) {
    __syncthreads();
    if (threadIdx.x == 0) {
        __threadfence();
        atomicAdd((unsigned*)(g_bar + id), 1u);
        while (g_bar[id] < (unsigned)NCSR) __nanosleep(128);
        __threadfence();
    }
    __syncthreads();
}

// ---------------- CSR build (runs in blocks [0,NCSR) of hybrid kernel) --------
__device__ void csr_build(const int* __restrict__ ei, const int* __restrict__ batch,
                          int n, int e) {
    int tid  = threadIdx.x;
    int gtid = blockIdx.x * 256 + tid;

    __shared__ int sm[8];
    __shared__ int s_carry;

    // phase 0: zero deg + pooling accumulators
    for (int i = gtid; i < n; i += CSR_THREADS) g_deg[i] = 0;
    if (gtid < NGR) { g_gsum[gtid] = 0.0f; g_cnt[gtid] = 0; }
    if (gtid == 0)  g_rowstart[n] = e;    // sum of in-degrees == e
    csr_barrier(0);

    // phase 1: histogram in-degrees + per-graph node counts
    for (int i = gtid; i < e; i += CSR_THREADS) atomicAdd(&g_deg[ei[e + i]], 1);
    for (int i = gtid; i < n; i += CSR_THREADS) atomicAdd(&g_cnt[batch[i]], 1);
    csr_barrier(1);

    // phase 2a: per-block chunk sums
    const int chunk = (n + NCSR - 1) / NCSR;
    int base = blockIdx.x * chunk;
    int lim  = n - base; if (lim > chunk) lim = chunk; if (lim < 0) lim = 0;

    int psum = 0;
    for (int i = tid; i < lim; i += 256) psum += __ldcg(&g_deg[base + i]);
    #pragma unroll
    for (int off = 16; off; off >>= 1) psum += __shfl_xor_sync(0xffffffffu, psum, off);
    if ((tid & 31) == 0) sm[tid >> 5] = psum;
    __syncthreads();
    if (tid == 0) {
        int s = 0;
        #pragma unroll
        for (int w = 0; w < 8; ++w) s += sm[w];
        g_blocksum[blockIdx.x] = s;
    }
    csr_barrier(2);

    // phase 2b: this block's global offset
    if (tid == 0) {
        int off = 0;
        for (int b = 0; b < blockIdx.x; ++b) off += __ldcg(&g_blocksum[b]);
        s_carry = off;
    }
    __syncthreads();
    int run = s_carry;
    __syncthreads();

    // phase 2c: exclusive scan of this chunk -> rowstart / cursor / dinv
    int lane = tid & 31, wid = tid >> 5;
    for (int o = 0; o < lim; o += 256) {
        int i = base + o + tid;
        int v = (o + tid < lim) ? __ldcg(&g_deg[i]) : 0;
        int x = v;
        #pragma unroll
        for (int off = 1; off < 32; off <<= 1) {
            int t = __shfl_up_sync(0xffffffffu, x, off);
            if (lane >= off) x += t;
        }
        if (lane == 31) sm[wid] = x;
        __syncthreads();
        if (wid == 0 && lane < 8) {
            int s = sm[lane];
            #pragma unroll
            for (int off = 1; off < 8; off <<= 1) {
                int t = __shfl_up_sync(0xffu, s, off);
                if (lane >= off) s += t;
            }
            sm[lane] = s;
        }
        __syncthreads();
        int woff = wid ? sm[wid - 1] : 0;
        if (o + tid < lim) {
            int excl = run + x + woff - v;
            g_rowstart[i] = excl;
            g_cursor[i]   = excl;
            g_dinv[i]     = rsqrtf((float)(v + 1));   // +1 self-loop
        }
        run += sm[7];
        __syncthreads();
    }
    csr_barrier(3);

    // phase 3: scatter edges into CSR
    for (int i = gtid; i < e; i += CSR_THREADS) {
        int s = ei[i];
        int d = ei[e + i];
        int p = atomicAdd(&g_cursor[d], 1);
        g_csr[p] = s;
    }
}

// ---------------- tf32 tensor-core GEMM --------------------------------------
__device__ __forceinline__ uint32_t f2tf(float f) {
    uint32_t r;
    asm("cvt.rna.tf32.f32 %0, %1;" : "=r"(r) : "f"(f));
    return r;
}

__device__ __forceinline__ void mma_tf32(float* c, const uint32_t* a, const uint32_t* b) {
    asm volatile(
        "mma.sync.aligned.m16n8k8.row.col.f32.tf32.tf32.f32 "
        "{%0,%1,%2,%3}, {%4,%5,%6,%7}, {%8,%9}, {%0,%1,%2,%3};\n"
        : "+f"(c[0]), "+f"(c[1]), "+f"(c[2]), "+f"(c[3])
        : "r"(a[0]), "r"(a[1]), "r"(a[2]), "r"(a[3]),
          "r"(b[0]), "r"(b[1]));
}

#define BM 128
#define BN 64
#define BKT 32

// Y[m,:] = (scale ? scale[m] : 1) * (A[m,:] @ B), register-prefetch double buffer.
// 256 threads = 8 warps (4M x 2N), each warp 32x32.
__device__ __forceinline__ void gemm_body(
    const float* __restrict__ A, const float* __restrict__ B,
    const float* __restrict__ scale, float* __restrict__ Y,
    int M, int K, int bid,
    uint32_t (*As)[36], uint32_t (*Bs)[72]) {

    int tid  = threadIdx.x;
    int lane = tid & 31, warp = tid >> 5;
    int wm = warp >> 1, wn = warp & 1;
    int gid = lane >> 2, tig = lane & 3;
    int m0 = (bid >> 2) * BM;
    int n0 = (bid & 3) * BN;

    float c[2][4][4] = {};
    float4 pa[4], pb[2];

    auto ldA = [&](int k0) {
        #pragma unroll
        for (int t = 0; t < 4; ++t) {
            int f4 = tid + t * 256;
            int r = f4 >> 3, cc = (f4 & 7) << 2;
            int gr = m0 + r;
            pa[t] = (gr < M) ? *(const float4*)(A + (size_t)gr * K + k0 + cc)
                             : make_float4(0.f, 0.f, 0.f, 0.f);
        }
    };
    auto ldB = [&](int k0) {
        #pragma unroll
        for (int t = 0; t < 2; ++t) {
            int f4 = tid + t * 256;
            int r = f4 >> 4, cc = (f4 & 15) << 2;
            pb[t] = *(const float4*)(B + (size_t)(k0 + r) * DH + n0 + cc);
        }
    };
    auto stTile = [&]() {
        #pragma unroll
        for (int t = 0; t < 4; ++t) {
            int f4 = tid + t * 256;
            int r = f4 >> 3, cc = (f4 & 7) << 2;
            As[r][cc + 0] = f2tf(pa[t].x);
            As[r][cc + 1] = f2tf(pa[t].y);
            As[r][cc + 2] = f2tf(pa[t].z);
            As[r][cc + 3] = f2tf(pa[t].w);
        }
        #pragma unroll
        for (int t = 0; t < 2; ++t) {
            int f4 = tid + t * 256;
            int r = f4 >> 4, cc = (f4 & 15) << 2;
            Bs[r][cc + 0] = f2tf(pb[t].x);
            Bs[r][cc + 1] = f2tf(pb[t].y);
            Bs[r][cc + 2] = f2tf(pb[t].z);
            Bs[r][cc + 3] = f2tf(pb[t].w);
        }
    };

    ldA(0); ldB(0); stTile();
    __syncthreads();

    int KT = K / BKT;
    for (int kt = 0; kt < KT; ++kt) {
        if (kt + 1 < KT) { ldA((kt + 1) * BKT); ldB((kt + 1) * BKT); }

        #pragma unroll
        for (int kk = 0; kk < BKT; kk += 8) {
            uint32_t a[2][4], b[4][2];
            #pragma unroll
            for (int i = 0; i < 2; ++i) {
                int mrow = wm * 32 + i * 16;
                a[i][0] = As[mrow + gid][kk + tig];
                a[i][1] = As[mrow + gid + 8][kk + tig];
                a[i][2] = As[mrow + gid][kk + tig + 4];
                a[i][3] = As[mrow + gid + 8][kk + tig + 4];
            }
            #pragma unroll
            for (int j = 0; j < 4; ++j) {
                int ncol = wn * 32 + j * 8 + gid;
                b[j][0] = Bs[kk + tig][ncol];
                b[j][1] = Bs[kk + tig + 4][ncol];
            }
            #pragma unroll
            for (int i = 0; i < 2; ++i)
                #pragma unroll
                for (int j = 0; j < 4; ++j)
                    mma_tf32(c[i][j], a[i], b[j]);
        }
        __syncthreads();
        if (kt + 1 < KT) { stTile(); __syncthreads(); }
    }

    // epilogue (optional per-row scale)
    #pragma unroll
    for (int i = 0; i < 2; ++i) {
        int r0 = m0 + wm * 32 + i * 16 + gid;
        int r1 = r0 + 8;
        float s0 = 1.f, s1 = 1.f;
        if (scale) {
            s0 = (r0 < M) ? scale[r0] : 0.f;
            s1 = (r1 < M) ? scale[r1] : 0.f;
        }
        #pragma unroll
        for (int j = 0; j < 4; ++j) {
            int cb = n0 + wn * 32 + j * 8 + tig * 2;
            if (r0 < M) {
                Y[(size_t)r0 * DH + cb]     = s0 * c[i][j][0];
                Y[(size_t)r0 * DH + cb + 1] = s0 * c[i][j][1];
            }
            if (r1 < M) {
                Y[(size_t)r1 * DH + cb]     = s1 * c[i][j][2];
                Y[(size_t)r1 * DH + cb + 1] = s1 * c[i][j][3];
            }
        }
    }
}

// hybrid: blocks [0,NCSR) build CSR; the rest compute Y = X @ W1 (unscaled)
__global__ __launch_bounds__(256)
void hybrid_kernel(const float* __restrict__ x, const float* __restrict__ W1,
                   float* __restrict__ y, int n,
                   const int* __restrict__ ei, const int* __restrict__ batch, int e) {
    __shared__ uint32_t As[BM][36];
    __shared__ uint32_t Bs[BKT][72];
    if (blockIdx.x < NCSR) { csr_build(ei, batch, n, e); return; }
    gemm_body(x, W1, nullptr, y, n, DIN, blockIdx.x - NCSR, As, Bs);
}

__global__ __launch_bounds__(256)
void gemm_kernel(const float* __restrict__ A, const float* __restrict__ B,
                 const float* __restrict__ scale, float* __restrict__ Y,
                 int M, int K) {
    __shared__ uint32_t As[BM][36];
    __shared__ uint32_t Bs[BKT][72];
    gemm_body(A, B, scale, Y, M, K, blockIdx.x, As, Bs);
}

// ---------------- warp-per-node gather aggregation ----------------------------
// layer 1: y holds UNscaled X@W1; apply dinv[src] per gathered row here.
// out[node,:] = relu( dinv[node] * (sum_src dinv[src]*y[src,:] + dinv[node]*y[node,:]) + bias )
__global__ __launch_bounds__(256)
void aggregate1_kernel(const float* __restrict__ y, const float* __restrict__ bias,
                       float* __restrict__ out, int n) {
    int gw   = (blockIdx.x * blockDim.x + threadIdx.x) >> 5;
    int lane = threadIdx.x & 31;
    if (gw >= n) return;
    int e0 = g_rowstart[gw], e1 = g_rowstart[gw + 1];

    float4 a0 = make_float4(0.f, 0.f, 0.f, 0.f);
    float4 a1 = make_float4(0.f, 0.f, 0.f, 0.f);

    int e = e0;
    for (; e + 4 <= e1; e += 4) {
        int s0 = g_csr[e], s1 = g_csr[e + 1], s2 = g_csr[e + 2], s3 = g_csr[e + 3];
        float d0 = g_dinv[s0], d1 = g_dinv[s1], d2 = g_dinv[s2], d3 = g_dinv[s3];
        const float4* p0 = (const float4*)(y + (size_t)s0 * DH) + lane;
        const float4* p1 = (const float4*)(y + (size_t)s1 * DH) + lane;
        const float4* p2 = (const float4*)(y + (size_t)s2 * DH) + lane;
        const float4* p3 = (const float4*)(y + (size_t)s3 * DH) + lane;
        float4 u0 = p0[0], w0 = p0[32];
        float4 u1 = p1[0], w1 = p1[32];
        float4 u2 = p2[0], w2 = p2[32];
        float4 u3 = p3[0], w3 = p3[32];
        a0.x += d0*u0.x + d1*u1.x + d2*u2.x + d3*u3.x;
        a0.y += d0*u0.y + d1*u1.y + d2*u2.y + d3*u3.y;
        a0.z += d0*u0.z + d1*u1.z + d2*u2.z + d3*u3.z;
        a0.w += d0*u0.w + d1*u1.w + d2*u2.w + d3*u3.w;
        a1.x += d0*w0.x + d1*w1.x + d2*w2.x + d3*w3.x;
        a1.y += d0*w0.y + d1*w1.y + d2*w2.y + d3*w3.y;
        a1.z += d0*w0.z + d1*w1.z + d2*w2.z + d3*w3.z;
        a1.w += d0*w0.w + d1*w1.w + d2*w2.w + d3*w3.w;
    }
    for (; e < e1; ++e) {
        int s = g_csr[e];
        float dv = g_dinv[s];
        const float4* p = (const float4*)(y + (size_t)s * DH) + lane;
        float4 u = p[0], w = p[32];
        a0.x += dv*u.x; a0.y += dv*u.y; a0.z += dv*u.z; a0.w += dv*u.w;
        a1.x += dv*w.x; a1.y += dv*w.y; a1.z += dv*w.z; a1.w += dv*w.w;
    }
    float dvn = g_dinv[gw];
    {   // self loop
        const float4* p = (const float4*)(y + (size_t)gw * DH) + lane;
        float4 u = p[0], w = p[32];
        a0.x += dvn*u.x; a0.y += dvn*u.y; a0.z += dvn*u.z; a0.w += dvn*u.w;
        a1.x += dvn*w.x; a1.y += dvn*w.y; a1.z += dvn*w.z; a1.w += dvn*w.w;
    }
    float4 b0 = ((const float4*)bias)[lane];
    float4 b1 = ((const float4*)bias)[32 + lane];
    float4 r0, r1;
    r0.x = fmaxf(dvn * a0.x + b0.x, 0.f); r0.y = fmaxf(dvn * a0.y + b0.y, 0.f);
    r0.z = fmaxf(dvn * a0.z + b0.z, 0.f); r0.w = fmaxf(dvn * a0.w + b0.w, 0.f);
    r1.x = fmaxf(dvn * a1.x + b1.x, 0.f); r1.y = fmaxf(dvn * a1.y + b1.y, 0.f);
    r1.z = fmaxf(dvn * a1.z + b1.z, 0.f); r1.w = fmaxf(dvn * a1.w + b1.w, 0.f);
    float4* op = (float4*)(out + (size_t)gw * DH) + lane;
    op[0]  = r0;
    op[32] = r1;
}

// layer-2 aggregate fused with pool+FC (y is pre-scaled by dinv[src] in gemm2 epilogue)
__global__ __launch_bounds__(256)
void aggregate2_pool_kernel(const float* __restrict__ y, const float* __restrict__ bias,
                            const float* __restrict__ wfc, const int* __restrict__ batch,
                            int n) {
    int gw   = (blockIdx.x * blockDim.x + threadIdx.x) >> 5;
    int lane = threadIdx.x & 31;
    if (gw >= n) return;
    int e0 = g_rowstart[gw], e1 = g_rowstart[gw + 1];

    float4 a0 = make_float4(0.f, 0.f, 0.f, 0.f);
    float4 a1 = make_float4(0.f, 0.f, 0.f, 0.f);

    int e = e0;
    for (; e + 4 <= e1; e += 4) {
        int s0 = g_csr[e], s1 = g_csr[e + 1], s2 = g_csr[e + 2], s3 = g_csr[e + 3];
        const float4* p0 = (const float4*)(y + (size_t)s0 * DH) + lane;
        const float4* p1 = (const float4*)(y + (size_t)s1 * DH) + lane;
        const float4* p2 = (const float4*)(y + (size_t)s2 * DH) + lane;
        const float4* p3 = (const float4*)(y + (size_t)s3 * DH) + lane;
        float4 u0 = p0[0], w0 = p0[32];
        float4 u1 = p1[0], w1 = p1[32];
        float4 u2 = p2[0], w2 = p2[32];
        float4 u3 = p3[0], w3 = p3[32];
        a0.x += u0.x + u1.x + u2.x + u3.x;  a0.y += u0.y + u1.y + u2.y + u3.y;
        a0.z += u0.z + u1.z + u2.z + u3.z;  a0.w += u0.w + u1.w + u2.w + u3.w;
        a1.x += w0.x + w1.x + w2.x + w3.x;  a1.y += w0.y + w1.y + w2.y + w3.y;
        a1.z += w0.z + w1.z + w2.z + w3.z;  a1.w += w0.w + w1.w + w2.w + w3.w;
    }
    for (; e < e1; ++e) {
        int s = g_csr[e];
        const float4* p = (const float4*)(y + (size_t)s * DH) + lane;
        float4 u = p[0], w = p[32];
        a0.x += u.x; a0.y += u.y; a0.z += u.z; a0.w += u.w;
        a1.x += w.x; a1.y += w.y; a1.z += w.z; a1.w += w.w;
    }
    {
        const float4* p = (const float4*)(y + (size_t)gw * DH) + lane;
        float4 u = p[0], w = p[32];
        a0.x += u.x; a0.y += u.y; a0.z += u.z; a0.w += u.w;
        a1.x += w.x; a1.y += w.y; a1.z += w.z; a1.w += w.w;
    }
    float dv = g_dinv[gw];
    float4 b0 = ((const float4*)bias)[lane];
    float4 b1 = ((const float4*)bias)[32 + lane];
    float4 f0 = ((const float4*)wfc)[lane];
    float4 f1 = ((const float4*)wfc)[32 + lane];

    float h;
    float dot = 0.f;
    h = fmaxf(dv * a0.x + b0.x, 0.f); dot += h * f0.x;
    h = fmaxf(dv * a0.y + b0.y, 0.f); dot += h * f0.y;
    h = fmaxf(dv * a0.z + b0.z, 0.f); dot += h * f0.z;
    h = fmaxf(dv * a0.w + b0.w, 0.f); dot += h * f0.w;
    h = fmaxf(dv * a1.x + b1.x, 0.f); dot += h * f1.x;
    h = fmaxf(dv * a1.y + b1.y, 0.f); dot += h * f1.y;
    h = fmaxf(dv * a1.z + b1.z, 0.f); dot += h * f1.z;
    h = fmaxf(dv * a1.w + b1.w, 0.f); dot += h * f1.w;

    #pragma unroll
    for (int off = 16; off > 0; off >>= 1)
        dot += __shfl_xor_sync(0xffffffffu, dot, off);
    if (lane == 0)
        atomicAdd(&g_gsum[batch[gw]], dot);
}

__global__ void finalize_kernel(float* __restrict__ out, const float* __restrict__ bfc) {
    int g = threadIdx.x;
    if (g < NGR)
        out[g] = g_gsum[g] / fmaxf((float)g_cnt[g], 1.0f) + bfc[0];
}

// ---------------- launch ------------------------------------------------------
extern "C" void kernel_launch(void* const* d_in, const int* in_sizes, int n_in,
                              void* d_out, int out_size) {
    const float* x     = (const float*)d_in[0];
    const int*   ei    = (const int*)  d_in[1];
    const int*   batch = (const int*)  d_in[2];
    const float* W1    = (const float*)d_in[3];
    const float* b1    = (const float*)d_in[4];
    const float* W2    = (const float*)d_in[5];
    const float* b2    = (const float*)d_in[6];
    const float* wfc   = (const float*)d_in[7];
    const float* bfc   = (const float*)d_in[8];
    float* out = (float*)d_out;

    int n = in_sizes[0] / DIN;   // 20000
    int e = in_sizes[1] / 2;     // 320000

    float* yptr = nullptr;
    float* hptr = nullptr;
    float* dinvptr = nullptr;
    cudaGetSymbolAddress((void**)&yptr, g_y);
    cudaGetSymbolAddress((void**)&hptr, g_h);
    cudaGetSymbolAddress((void**)&dinvptr, g_dinv);

    int gblocks = ((n + BM - 1) / BM) * 4;   // M-blocks x 4 N-blocks

    reset_bar_kernel<<<1, 32>>>();

    hybrid_kernel<<<NCSR + gblocks, 256>>>(x, W1, yptr, n, ei, batch, e);

    int ta = ((n * 32) + 255) / 256;
    aggregate1_kernel<<<ta, 256>>>(yptr, b1, hptr, n);

    gemm_kernel<<<gblocks, 256>>>(hptr, W2, dinvptr, yptr, n, DH);

    aggregate2_pool_kernel<<<ta, 256>>>(yptr, b2, wfc, batch, n);

    finalize_kernel<<<1, NGR>>>(out, bfc);
}

// round 7
// speedup vs baseline: 1.3737x; 1.2880x over previous
#include <cuda_runtime.h>
#include <cuda_bf16.h>
#include <cstdint>

// Problem constants (fixed by dataset)
#define NMAX   20000
#define EMAX   320000
#define DIN    512
#define DH     256
#define NGR    128
#define NCSR   64                      // CSR-builder blocks inside hybrid kernel
#define CSR_THREADS (NCSR * 256)

// ---------------- scratch (static device globals; no runtime alloc) ----------
__device__ int   g_deg[NMAX];
__device__ int   g_rowstart[NMAX + 1];
__device__ int   g_cursor[NMAX];
__device__ int   g_csr[EMAX];
__device__ float g_dinv[NMAX];
__device__ __align__(16) __nv_bfloat16 g_yb[(size_t)NMAX * DH];  // bf16 gather source
__device__ __align__(16) float g_h[(size_t)NMAX * DH];           // layer-1 hidden (fp32)
__device__ float g_gsum[NGR];
__device__ int   g_cnt[NGR];
__device__ int   g_blocksum[NCSR];
__device__ volatile unsigned g_bar[4];

// ---------------- reset (must run before each hybrid launch) ------------------
__global__ void reset_bar_kernel() {
    if (threadIdx.x < 4) g_bar[threadIdx.x] = 0u;
}

// ---------------- spin barrier among the NCSR builder blocks ------------------
__device__ __forceinline__ void csr_barrier(int id) {
    __syncthreads();
    if (threadIdx.x == 0) {
        __threadfence();
        atomicAdd((unsigned*)(g_bar + id), 1u);
        while (g_bar[id] < (unsigned)NCSR) __nanosleep(128);
        __threadfence();
    }
    __syncthreads();
}

// ---------------- CSR build (runs in blocks [0,NCSR) of hybrid kernel) --------
__device__ void csr_build(const int* __restrict__ ei, const int* __restrict__ batch,
                          int n, int e) {
    int tid  = threadIdx.x;
    int gtid = blockIdx.x * 256 + tid;

    __shared__ int sm[8];
    __shared__ int s_carry;

    // phase 0: zero deg + pooling accumulators
    for (int i = gtid; i < n; i += CSR_THREADS) g_deg[i] = 0;
    if (gtid < NGR) { g_gsum[gtid] = 0.0f; g_cnt[gtid] = 0; }
    if (gtid == 0)  g_rowstart[n] = e;    // sum of in-degrees == e
    csr_barrier(0);

    // phase 1: histogram in-degrees + per-graph node counts
    for (int i = gtid; i < e; i += CSR_THREADS) atomicAdd(&g_deg[ei[e + i]], 1);
    for (int i = gtid; i < n; i += CSR_THREADS) atomicAdd(&g_cnt[batch[i]], 1);
    csr_barrier(1);

    // phase 2a: per-block chunk sums
    const int chunk = (n + NCSR - 1) / NCSR;
    int base = blockIdx.x * chunk;
    int lim  = n - base; if (lim > chunk) lim = chunk; if (lim < 0) lim = 0;

    int psum = 0;
    for (int i = tid; i < lim; i += 256) psum += __ldcg(&g_deg[base + i]);
    #pragma unroll
    for (int off = 16; off; off >>= 1) psum += __shfl_xor_sync(0xffffffffu, psum, off);
    if ((tid & 31) == 0) sm[tid >> 5] = psum;
    __syncthreads();
    if (tid == 0) {
        int s = 0;
        #pragma unroll
        for (int w = 0; w < 8; ++w) s += sm[w];
        g_blocksum[blockIdx.x] = s;
    }
    csr_barrier(2);

    // phase 2b: this block's global offset
    if (tid == 0) {
        int off = 0;
        for (int b = 0; b < blockIdx.x; ++b) off += __ldcg(&g_blocksum[b]);
        s_carry = off;
    }
    __syncthreads();
    int run = s_carry;
    __syncthreads();

    // phase 2c: exclusive scan of this chunk -> rowstart / cursor / dinv
    int lane = tid & 31, wid = tid >> 5;
    for (int o = 0; o < lim; o += 256) {
        int i = base + o + tid;
        int v = (o + tid < lim) ? __ldcg(&g_deg[i]) : 0;
        int x = v;
        #pragma unroll
        for (int off = 1; off < 32; off <<= 1) {
            int t = __shfl_up_sync(0xffffffffu, x, off);
            if (lane >= off) x += t;
        }
        if (lane == 31) sm[wid] = x;
        __syncthreads();
        if (wid == 0 && lane < 8) {
            int s = sm[lane];
            #pragma unroll
            for (int off = 1; off < 8; off <<= 1) {
                int t = __shfl_up_sync(0xffu, s, off);
                if (lane >= off) s += t;
            }
            sm[lane] = s;
        }
        __syncthreads();
        int woff = wid ? sm[wid - 1] : 0;
        if (o + tid < lim) {
            int excl = run + x + woff - v;
            g_rowstart[i] = excl;
            g_cursor[i]   = excl;
            g_dinv[i]     = rsqrtf((float)(v + 1));   // +1 self-loop
        }
        run += sm[7];
        __syncthreads();
    }
    csr_barrier(3);

    // phase 3: scatter edges into CSR
    for (int i = gtid; i < e; i += CSR_THREADS) {
        int s = ei[i];
        int d = ei[e + i];
        int p = atomicAdd(&g_cursor[d], 1);
        g_csr[p] = s;
    }
}

// ---------------- tf32 tensor-core GEMM --------------------------------------
__device__ __forceinline__ uint32_t f2tf(float f) {
    uint32_t r;
    asm("cvt.rna.tf32.f32 %0, %1;" : "=r"(r) : "f"(f));
    return r;
}

__device__ __forceinline__ void mma_tf32(float* c, const uint32_t* a, const uint32_t* b) {
    asm volatile(
        "mma.sync.aligned.m16n8k8.row.col.f32.tf32.tf32.f32 "
        "{%0,%1,%2,%3}, {%4,%5,%6,%7}, {%8,%9}, {%0,%1,%2,%3};\n"
        : "+f"(c[0]), "+f"(c[1]), "+f"(c[2]), "+f"(c[3])
        : "r"(a[0]), "r"(a[1]), "r"(a[2]), "r"(a[3]),
          "r"(b[0]), "r"(b[1]));
}

#define BM 128
#define BN 128
#define BKT 32
#define BSPAD 136   // 136 % 32 = 8 -> b-frag loads (tig*8+gid) hit all 32 banks

// Yb[m,:] = bf16( (scale ? scale[m] : 1) * (A[m,:] @ B) )
// 256 threads = 8 warps (2M x 4N), each warp computes 64x32 (i=4, j=4).
__device__ __forceinline__ void gemm_body(
    const float* __restrict__ A, const float* __restrict__ B,
    const float* __restrict__ scale, __nv_bfloat16* __restrict__ Yb,
    int M, int K, int bid,
    uint32_t (*As)[36], uint32_t (*Bs)[BSPAD]) {

    int tid  = threadIdx.x;
    int lane = tid & 31, warp = tid >> 5;
    int wm = warp >> 2, wn = warp & 3;
    int gid = lane >> 2, tig = lane & 3;
    int m0 = (bid >> 1) * BM;
    int n0 = (bid & 1) * BN;

    float c[4][4][4] = {};
    float4 pa[4], pb[4];

    auto ldA = [&](int k0) {
        #pragma unroll
        for (int t = 0; t < 4; ++t) {
            int f4 = tid + t * 256;
            int r = f4 >> 3, cc = (f4 & 7) << 2;
            int gr = m0 + r;
            pa[t] = (gr < M) ? *(const float4*)(A + (size_t)gr * K + k0 + cc)
                             : make_float4(0.f, 0.f, 0.f, 0.f);
        }
    };
    auto ldB = [&](int k0) {
        #pragma unroll
        for (int t = 0; t < 4; ++t) {
            int f4 = tid + t * 256;
            int r = f4 >> 5, cc = (f4 & 31) << 2;
            pb[t] = *(const float4*)(B + (size_t)(k0 + r) * DH + n0 + cc);
        }
    };
    auto stTile = [&]() {
        #pragma unroll
        for (int t = 0; t < 4; ++t) {
            int f4 = tid + t * 256;
            int r = f4 >> 3, cc = (f4 & 7) << 2;
            *(uint4*)&As[r][cc] = make_uint4(f2tf(pa[t].x), f2tf(pa[t].y),
                                             f2tf(pa[t].z), f2tf(pa[t].w));
        }
        #pragma unroll
        for (int t = 0; t < 4; ++t) {
            int f4 = tid + t * 256;
            int r = f4 >> 5, cc = (f4 & 31) << 2;
            *(uint4*)&Bs[r][cc] = make_uint4(f2tf(pb[t].x), f2tf(pb[t].y),
                                             f2tf(pb[t].z), f2tf(pb[t].w));
        }
    };

    ldA(0); ldB(0); stTile();
    __syncthreads();

    int KT = K / BKT;
    for (int kt = 0; kt < KT; ++kt) {
        if (kt + 1 < KT) { ldA((kt + 1) * BKT); ldB((kt + 1) * BKT); }

        #pragma unroll
        for (int kk = 0; kk < BKT; kk += 8) {
            uint32_t a[4][4], b[4][2];
            #pragma unroll
            for (int i = 0; i < 4; ++i) {
                int mrow = wm * 64 + i * 16;
                a[i][0] = As[mrow + gid][kk + tig];
                a[i][1] = As[mrow + gid + 8][kk + tig];
                a[i][2] = As[mrow + gid][kk + tig + 4];
                a[i][3] = As[mrow + gid + 8][kk + tig + 4];
            }
            #pragma unroll
            for (int j = 0; j < 4; ++j) {
                int ncol = wn * 32 + j * 8 + gid;
                b[j][0] = Bs[kk + tig][ncol];
                b[j][1] = Bs[kk + tig + 4][ncol];
            }
            #pragma unroll
            for (int i = 0; i < 4; ++i)
                #pragma unroll
                for (int j = 0; j < 4; ++j)
                    mma_tf32(c[i][j], a[i], b[j]);
        }
        __syncthreads();
        if (kt + 1 < KT) { stTile(); __syncthreads(); }
    }

    // epilogue: optional per-row scale, then bf16 pack + store
    #pragma unroll
    for (int i = 0; i < 4; ++i) {
        int r0 = m0 + wm * 64 + i * 16 + gid;
        int r1 = r0 + 8;
        float s0 = 1.f, s1 = 1.f;
        if (scale) {
            s0 = (r0 < M) ? scale[r0] : 0.f;
            s1 = (r1 < M) ? scale[r1] : 0.f;
        }
        #pragma unroll
        for (int j = 0; j < 4; ++j) {
            int cb = n0 + wn * 32 + j * 8 + tig * 2;
            if (r0 < M) {
                __nv_bfloat162 v = __float22bfloat162_rn(
                    make_float2(s0 * c[i][j][0], s0 * c[i][j][1]));
                *(__nv_bfloat162*)(Yb + (size_t)r0 * DH + cb) = v;
            }
            if (r1 < M) {
                __nv_bfloat162 v = __float22bfloat162_rn(
                    make_float2(s1 * c[i][j][2], s1 * c[i][j][3]));
                *(__nv_bfloat162*)(Yb + (size_t)r1 * DH + cb) = v;
            }
        }
    }
}

// hybrid: blocks [0,NCSR) build CSR; the rest compute Yb = bf16(X @ W1) (unscaled)
__global__ __launch_bounds__(256, 1)
void hybrid_kernel(const float* __restrict__ x, const float* __restrict__ W1,
                   __nv_bfloat16* __restrict__ yb, int n,
                   const int* __restrict__ ei, const int* __restrict__ batch, int e) {
    __shared__ __align__(16) uint32_t As[BM][36];
    __shared__ __align__(16) uint32_t Bs[BKT][BSPAD];
    if (blockIdx.x < NCSR) { csr_build(ei, batch, n, e); return; }
    gemm_body(x, W1, nullptr, yb, n, DIN, blockIdx.x - NCSR, As, Bs);
}

__global__ __launch_bounds__(256, 1)
void gemm_kernel(const float* __restrict__ A, const float* __restrict__ B,
                 const float* __restrict__ scale, __nv_bfloat16* __restrict__ Yb,
                 int M, int K) {
    __shared__ __align__(16) uint32_t As[BM][36];
    __shared__ __align__(16) uint32_t Bs[BKT][BSPAD];
    gemm_body(A, B, scale, Yb, M, K, blockIdx.x, As, Bs);
}

// ---------------- warp-per-node gather aggregation (bf16 source) --------------
// Each lane owns 8 consecutive channels (one uint4 = 8 bf16 per gathered row).
__device__ __forceinline__ void acc8(float* acc, uint4 v, float dv) {
    const __nv_bfloat162* b = reinterpret_cast<const __nv_bfloat162*>(&v);
    #pragma unroll
    for (int q = 0; q < 4; ++q) {
        float2 f = __bfloat1622float2(b[q]);
        acc[2 * q]     = fmaf(dv, f.x, acc[2 * q]);
        acc[2 * q + 1] = fmaf(dv, f.y, acc[2 * q + 1]);
    }
}

// layer 1: yb holds UNscaled bf16(X@W1); apply dinv[src] per gathered row.
// h[node,:] = relu( dinv[node]*(sum_src dinv[src]*y[src,:] + dinv[node]*y[node,:]) + b1 )
__global__ __launch_bounds__(256)
void aggregate1_kernel(const __nv_bfloat16* __restrict__ yb,
                       const float* __restrict__ bias,
                       float* __restrict__ out, int n) {
    int gw   = (blockIdx.x * blockDim.x + threadIdx.x) >> 5;
    int lane = threadIdx.x & 31;
    if (gw >= n) return;
    int e0 = g_rowstart[gw], e1 = g_rowstart[gw + 1];

    float acc[8] = {};

    int e = e0;
    for (; e + 4 <= e1; e += 4) {
        int s0 = g_csr[e], s1 = g_csr[e + 1], s2 = g_csr[e + 2], s3 = g_csr[e + 3];
        float d0 = g_dinv[s0], d1 = g_dinv[s1], d2 = g_dinv[s2], d3 = g_dinv[s3];
        uint4 v0 = ((const uint4*)(yb + (size_t)s0 * DH))[lane];
        uint4 v1 = ((const uint4*)(yb + (size_t)s1 * DH))[lane];
        uint4 v2 = ((const uint4*)(yb + (size_t)s2 * DH))[lane];
        uint4 v3 = ((const uint4*)(yb + (size_t)s3 * DH))[lane];
        acc8(acc, v0, d0); acc8(acc, v1, d1); acc8(acc, v2, d2); acc8(acc, v3, d3);
    }
    for (; e < e1; ++e) {
        int s = g_csr[e];
        uint4 v = ((const uint4*)(yb + (size_t)s * DH))[lane];
        acc8(acc, v, g_dinv[s]);
    }
    float dvn = g_dinv[gw];
    {   // self loop
        uint4 v = ((const uint4*)(yb + (size_t)gw * DH))[lane];
        acc8(acc, v, dvn);
    }
    float4 b0 = ((const float4*)bias)[2 * lane];
    float4 b1 = ((const float4*)bias)[2 * lane + 1];
    float4 r0, r1;
    r0.x = fmaxf(dvn * acc[0] + b0.x, 0.f); r0.y = fmaxf(dvn * acc[1] + b0.y, 0.f);
    r0.z = fmaxf(dvn * acc[2] + b0.z, 0.f); r0.w = fmaxf(dvn * acc[3] + b0.w, 0.f);
    r1.x = fmaxf(dvn * acc[4] + b1.x, 0.f); r1.y = fmaxf(dvn * acc[5] + b1.y, 0.f);
    r1.z = fmaxf(dvn * acc[6] + b1.z, 0.f); r1.w = fmaxf(dvn * acc[7] + b1.w, 0.f);
    float4* op = (float4*)(out + (size_t)gw * DH);
    op[2 * lane]     = r0;
    op[2 * lane + 1] = r1;
}

// layer-2 aggregate fused with pool+FC (yb is pre-scaled by dinv[src] in gemm2 epilogue)
__global__ __launch_bounds__(256)
void aggregate2_pool_kernel(const __nv_bfloat16* __restrict__ yb,
                            const float* __restrict__ bias,
                            const float* __restrict__ wfc,
                            const int* __restrict__ batch, int n) {
    int gw   = (blockIdx.x * blockDim.x + threadIdx.x) >> 5;
    int lane = threadIdx.x & 31;
    if (gw >= n) return;
    int e0 = g_rowstart[gw], e1 = g_rowstart[gw + 1];

    float acc[8] = {};

    int e = e0;
    for (; e + 4 <= e1; e += 4) {
        int s0 = g_csr[e], s1 = g_csr[e + 1], s2 = g_csr[e + 2], s3 = g_csr[e + 3];
        uint4 v0 = ((const uint4*)(yb + (size_t)s0 * DH))[lane];
        uint4 v1 = ((const uint4*)(yb + (size_t)s1 * DH))[lane];
        uint4 v2 = ((const uint4*)(yb + (size_t)s2 * DH))[lane];
        uint4 v3 = ((const uint4*)(yb + (size_t)s3 * DH))[lane];
        acc8(acc, v0, 1.f); acc8(acc, v1, 1.f); acc8(acc, v2, 1.f); acc8(acc, v3, 1.f);
    }
    for (; e < e1; ++e) {
        int s = g_csr[e];
        uint4 v = ((const uint4*)(yb + (size_t)s * DH))[lane];
        acc8(acc, v, 1.f);
    }
    {
        uint4 v = ((const uint4*)(yb + (size_t)gw * DH))[lane];
        acc8(acc, v, 1.f);
    }
    float dv = g_dinv[gw];
    float4 b0 = ((const float4*)bias)[2 * lane];
    float4 b1 = ((const float4*)bias)[2 * lane + 1];
    float4 f0 = ((const float4*)wfc)[2 * lane];
    float4 f1 = ((const float4*)wfc)[2 * lane + 1];

    float h;
    float dot = 0.f;
    h = fmaxf(dv * acc[0] + b0.x, 0.f); dot += h * f0.x;
    h = fmaxf(dv * acc[1] + b0.y, 0.f); dot += h * f0.y;
    h = fmaxf(dv * acc[2] + b0.z, 0.f); dot += h * f0.z;
    h = fmaxf(dv * acc[3] + b0.w, 0.f); dot += h * f0.w;
    h = fmaxf(dv * acc[4] + b1.x, 0.f); dot += h * f1.x;
    h = fmaxf(dv * acc[5] + b1.y, 0.f); dot += h * f1.y;
    h = fmaxf(dv * acc[6] + b1.z, 0.f); dot += h * f1.z;
    h = fmaxf(dv * acc[7] + b1.w, 0.f); dot += h * f1.w;

    #pragma unroll
    for (int off = 16; off > 0; off >>= 1)
        dot += __shfl_xor_sync(0xffffffffu, dot, off);
    if (lane == 0)
        atomicAdd(&g_gsum[batch[gw]], dot);
}

__global__ void finalize_kernel(float* __restrict__ out, const float* __restrict__ bfc) {
    int g = threadIdx.x;
    if (g < NGR)
        out[g] = g_gsum[g] / fmaxf((float)g_cnt[g], 1.0f) + bfc[0];
}

// ---------------- launch ------------------------------------------------------
extern "C" void kernel_launch(void* const* d_in, const int* in_sizes, int n_in,
                              void* d_out, int out_size) {
    const float* x     = (const float*)d_in[0];
    const int*   ei    = (const int*)  d_in[1];
    const int*   batch = (const int*)  d_in[2];
    const float* W1    = (const float*)d_in[3];
    const float* b1    = (const float*)d_in[4];
    const float* W2    = (const float*)d_in[5];
    const float* b2    = (const float*)d_in[6];
    const float* wfc   = (const float*)d_in[7];
    const float* bfc   = (const float*)d_in[8];
    float* out = (float*)d_out;

    int n = in_sizes[0] / DIN;   // 20000
    int e = in_sizes[1] / 2;     // 320000

    __nv_bfloat16* ybptr = nullptr;
    float* hptr = nullptr;
    float* dinvptr = nullptr;
    cudaGetSymbolAddress((void**)&ybptr, g_yb);
    cudaGetSymbolAddress((void**)&hptr, g_h);
    cudaGetSymbolAddress((void**)&dinvptr, g_dinv);

    int gblocks = ((n + BM - 1) / BM) * (DH / BN);   // 157 * 2 = 314

    reset_bar_kernel<<<1, 32>>>();

    hybrid_kernel<<<NCSR + gblocks, 256>>>(x, W1, ybptr, n, ei, batch, e);

    int ta = ((n * 32) + 255) / 256;
    aggregate1_kernel<<<ta, 256>>>(ybptr, b1, hptr, n);

    gemm_kernel<<<gblocks, 256>>>(hptr, W2, dinvptr, ybptr, n, DH);

    aggregate2_pool_kernel<<<ta, 256>>>(ybptr, b2, wfc, batch, n);

    finalize_kernel<<<1, NGR>>>(out, bfc);
}

// round 8
// speedup vs baseline: 1.4139x; 1.0293x over previous
#include <cuda_runtime.h>
#include <cuda_bf16.h>
#include <cstdint>

// Problem constants (fixed by dataset)
#define NMAX   20000
#define EMAX   320000
#define DIN    512
#define DH     256
#define NGR    128
#define NCSR   128                     // CSR-builder blocks inside hybrid kernel
#define CSR_THREADS (NCSR * 128)

// ---------------- scratch (static device globals; no runtime alloc) ----------
__device__ int   g_deg[NMAX];
__device__ int   g_rowstart[NMAX + 1];
__device__ int   g_cursor[NMAX];
__device__ int   g_csr[EMAX];
__device__ float g_dinv[NMAX];
__device__ __align__(16) __nv_bfloat16 g_yb[(size_t)NMAX * DH];  // bf16 gather source
__device__ __align__(16) float g_h[(size_t)NMAX * DH];           // layer-1 hidden (fp32)
__device__ float g_gsum[NGR];
__device__ int   g_cnt[NGR];
__device__ int   g_blocksum[NCSR];
__device__ volatile unsigned g_bar[4];

// ---------------- reset (must run before each hybrid launch) ------------------
__global__ void reset_bar_kernel() {
    if (threadIdx.x < 4) g_bar[threadIdx.x] = 0u;
}

// ---------------- spin barrier among the NCSR builder blocks ------------------
__device__ __forceinline__ void csr_barrier(int id) {
    __syncthreads();
    if (threadIdx.x == 0) {
        __threadfence();
        atomicAdd((unsigned*)(g_bar + id), 1u);
        while (g_bar[id] < (unsigned)NCSR) __nanosleep(128);
        __threadfence();
    }
    __syncthreads();
}

// ---------------- CSR build (blocks [0,NCSR) of hybrid kernel; 128 threads) ---
__device__ void csr_build(const int* __restrict__ ei, const int* __restrict__ batch,
                          int n, int e) {
    int tid  = threadIdx.x;                    // 0..127
    int gtid = blockIdx.x * 128 + tid;

    __shared__ int sm[4];
    __shared__ int s_carry;

    // phase 0: zero deg + pooling accumulators
    for (int i = gtid; i < n; i += CSR_THREADS) g_deg[i] = 0;
    if (gtid < NGR) { g_gsum[gtid] = 0.0f; g_cnt[gtid] = 0; }
    if (gtid == 0)  g_rowstart[n] = e;    // sum of in-degrees == e
    csr_barrier(0);

    // phase 1: histogram in-degrees + per-graph node counts
    for (int i = gtid; i < e; i += CSR_THREADS) atomicAdd(&g_deg[ei[e + i]], 1);
    for (int i = gtid; i < n; i += CSR_THREADS) atomicAdd(&g_cnt[batch[i]], 1);
    csr_barrier(1);

    const int chunk = (n + NCSR - 1) / NCSR;   // 157
    int base = blockIdx.x * chunk;
    int lim  = n - base; if (lim > chunk) lim = chunk; if (lim < 0) lim = 0;

    int lane = tid & 31, wid = tid >> 5;       // wid 0..3

    // phase 2a: per-block chunk sum
    int psum = 0;
    for (int i = tid; i < lim; i += 128) psum += __ldcg(&g_deg[base + i]);
    #pragma unroll
    for (int off = 16; off; off >>= 1) psum += __shfl_xor_sync(0xffffffffu, psum, off);
    if (lane == 0) sm[wid] = psum;
    __syncthreads();
    if (tid == 0) g_blocksum[blockIdx.x] = sm[0] + sm[1] + sm[2] + sm[3];
    csr_barrier(2);

    // phase 2b: parallel sum of predecessor blocksums -> this block's offset
    {
        int val = (tid < blockIdx.x) ? __ldcg(&g_blocksum[tid]) : 0;  // tid<128=NCSR
        #pragma unroll
        for (int off = 16; off; off >>= 1) val += __shfl_xor_sync(0xffffffffu, val, off);
        if (lane == 0) sm[wid] = val;
        __syncthreads();
        if (tid == 0) s_carry = sm[0] + sm[1] + sm[2] + sm[3];
        __syncthreads();
    }
    int run = s_carry;
    __syncthreads();

    // phase 2c: exclusive scan of this chunk -> rowstart / cursor / dinv
    for (int o = 0; o < lim; o += 128) {
        int i = base + o + tid;
        int v = (o + tid < lim) ? __ldcg(&g_deg[i]) : 0;
        int x = v;
        #pragma unroll
        for (int off = 1; off < 32; off <<= 1) {
            int t = __shfl_up_sync(0xffffffffu, x, off);
            if (lane >= off) x += t;
        }
        if (lane == 31) sm[wid] = x;
        __syncthreads();
        if (wid == 0 && lane < 4) {
            int s = sm[lane];
            #pragma unroll
            for (int off = 1; off < 4; off <<= 1) {
                int t = __shfl_up_sync(0xfu, s, off);
                if (lane >= off) s += t;
            }
            sm[lane] = s;
        }
        __syncthreads();
        int woff = wid ? sm[wid - 1] : 0;
        if (o + tid < lim) {
            int excl = run + x + woff - v;
            g_rowstart[i] = excl;
            g_cursor[i]   = excl;
            g_dinv[i]     = rsqrtf((float)(v + 1));   // +1 self-loop
        }
        run += sm[3];
        __syncthreads();
    }
    csr_barrier(3);

    // phase 3: scatter edges into CSR
    for (int i = gtid; i < e; i += CSR_THREADS) {
        int s = ei[i];
        int d = ei[e + i];
        int p = atomicAdd(&g_cursor[d], 1);
        g_csr[p] = s;
    }
}

// ---------------- tf32 tensor-core GEMM --------------------------------------
__device__ __forceinline__ uint32_t f2tf(float f) {
    uint32_t r;
    asm("cvt.rna.tf32.f32 %0, %1;" : "=r"(r) : "f"(f));
    return r;
}

__device__ __forceinline__ void mma_tf32(float* c, const uint32_t* a, const uint32_t* b) {
    asm volatile(
        "mma.sync.aligned.m16n8k8.row.col.f32.tf32.tf32.f32 "
        "{%0,%1,%2,%3}, {%4,%5,%6,%7}, {%8,%9}, {%0,%1,%2,%3};\n"
        : "+f"(c[0]), "+f"(c[1]), "+f"(c[2]), "+f"(c[3])
        : "r"(a[0]), "r"(a[1]), "r"(a[2]), "r"(a[3]),
          "r"(b[0]), "r"(b[1]));
}

#define BM 128
#define BN 64
#define BKT 32
#define ASPAD 36    // a-frag loads (4*gid + tig) hit all 32 banks
#define BSPAD 72    // b-frag loads (8*tig + gid) hit all 32 banks

// Yb[m,:] = bf16( (scale ? scale[m] : 1) * (A[m,:] @ B) )
// 128 threads = 4 warps (2M x 2N), each warp computes 64x32 (i=4, j=4).
__device__ __forceinline__ void gemm_body(
    const float* __restrict__ A, const float* __restrict__ B,
    const float* __restrict__ scale, __nv_bfloat16* __restrict__ Yb,
    int M, int K, int bid,
    uint32_t (*As)[ASPAD], uint32_t (*Bs)[BSPAD]) {

    int tid  = threadIdx.x;
    int lane = tid & 31, warp = tid >> 5;     // warp 0..3
    int wm = warp >> 1, wn = warp & 1;
    int gid = lane >> 2, tig = lane & 3;
    int m0 = (bid >> 2) * BM;
    int n0 = (bid & 3) * BN;

    float c[4][4][4] = {};
    float4 pa[8], pb[4];

    auto ldA = [&](int k0) {
        #pragma unroll
        for (int t = 0; t < 8; ++t) {
            int f4 = tid + t * 128;
            int r = f4 >> 3, cc = (f4 & 7) << 2;
            int gr = m0 + r;
            pa[t] = (gr < M) ? *(const float4*)(A + (size_t)gr * K + k0 + cc)
                             : make_float4(0.f, 0.f, 0.f, 0.f);
        }
    };
    auto ldB = [&](int k0) {
        #pragma unroll
        for (int t = 0; t < 4; ++t) {
            int f4 = tid + t * 128;
            int r = f4 >> 4, cc = (f4 & 15) << 2;
            pb[t] = *(const float4*)(B + (size_t)(k0 + r) * DH + n0 + cc);
        }
    };
    auto stTile = [&]() {
        #pragma unroll
        for (int t = 0; t < 8; ++t) {
            int f4 = tid + t * 128;
            int r = f4 >> 3, cc = (f4 & 7) << 2;
            *(uint4*)&As[r][cc] = make_uint4(f2tf(pa[t].x), f2tf(pa[t].y),
                                             f2tf(pa[t].z), f2tf(pa[t].w));
        }
        #pragma unroll
        for (int t = 0; t < 4; ++t) {
            int f4 = tid + t * 128;
            int r = f4 >> 4, cc = (f4 & 15) << 2;
            *(uint4*)&Bs[r][cc] = make_uint4(f2tf(pb[t].x), f2tf(pb[t].y),
                                             f2tf(pb[t].z), f2tf(pb[t].w));
        }
    };

    ldA(0); ldB(0); stTile();
    __syncthreads();

    int KT = K / BKT;
    for (int kt = 0; kt < KT; ++kt) {
        if (kt + 1 < KT) { ldA((kt + 1) * BKT); ldB((kt + 1) * BKT); }

        #pragma unroll
        for (int kk = 0; kk < BKT; kk += 8) {
            uint32_t a[4][4], b[4][2];
            #pragma unroll
            for (int i = 0; i < 4; ++i) {
                int mrow = wm * 64 + i * 16;
                a[i][0] = As[mrow + gid][kk + tig];
                a[i][1] = As[mrow + gid + 8][kk + tig];
                a[i][2] = As[mrow + gid][kk + tig + 4];
                a[i][3] = As[mrow + gid + 8][kk + tig + 4];
            }
            #pragma unroll
            for (int j = 0; j < 4; ++j) {
                int ncol = wn * 32 + j * 8 + gid;
                b[j][0] = Bs[kk + tig][ncol];
                b[j][1] = Bs[kk + tig + 4][ncol];
            }
            #pragma unroll
            for (int i = 0; i < 4; ++i)
                #pragma unroll
                for (int j = 0; j < 4; ++j)
                    mma_tf32(c[i][j], a[i], b[j]);
        }
        __syncthreads();
        if (kt + 1 < KT) { stTile(); __syncthreads(); }
    }

    // epilogue: optional per-row scale, then bf16 pack + store
    #pragma unroll
    for (int i = 0; i < 4; ++i) {
        int r0 = m0 + wm * 64 + i * 16 + gid;
        int r1 = r0 + 8;
        float s0 = 1.f, s1 = 1.f;
        if (scale) {
            s0 = (r0 < M) ? scale[r0] : 0.f;
            s1 = (r1 < M) ? scale[r1] : 0.f;
        }
        #pragma unroll
        for (int j = 0; j < 4; ++j) {
            int cb = n0 + wn * 32 + j * 8 + tig * 2;
            if (r0 < M) {
                __nv_bfloat162 v = __float22bfloat162_rn(
                    make_float2(s0 * c[i][j][0], s0 * c[i][j][1]));
                *(__nv_bfloat162*)(Yb + (size_t)r0 * DH + cb) = v;
            }
            if (r1 < M) {
                __nv_bfloat162 v = __float22bfloat162_rn(
                    make_float2(s1 * c[i][j][2], s1 * c[i][j][3]));
                *(__nv_bfloat162*)(Yb + (size_t)r1 * DH + cb) = v;
            }
        }
    }
}

// hybrid: blocks [0,NCSR) build CSR; the rest compute Yb = bf16(X @ W1) (unscaled)
__global__ __launch_bounds__(128, 2)
void hybrid_kernel(const float* __restrict__ x, const float* __restrict__ W1,
                   __nv_bfloat16* __restrict__ yb, int n,
                   const int* __restrict__ ei, const int* __restrict__ batch, int e) {
    __shared__ __align__(16) uint32_t As[BM][ASPAD];
    __shared__ __align__(16) uint32_t Bs[BKT][BSPAD];
    if (blockIdx.x < NCSR) { csr_build(ei, batch, n, e); return; }
    gemm_body(x, W1, nullptr, yb, n, DIN, blockIdx.x - NCSR, As, Bs);
}

__global__ __launch_bounds__(128, 2)
void gemm_kernel(const float* __restrict__ A, const float* __restrict__ B,
                 const float* __restrict__ scale, __nv_bfloat16* __restrict__ Yb,
                 int M, int K) {
    __shared__ __align__(16) uint32_t As[BM][ASPAD];
    __shared__ __align__(16) uint32_t Bs[BKT][BSPAD];
    gemm_body(A, B, scale, Yb, M, K, blockIdx.x, As, Bs);
}

// ---------------- warp-per-node gather aggregation (bf16 source) --------------
// Each lane owns 8 consecutive channels (one uint4 = 8 bf16 per gathered row).
__device__ __forceinline__ void acc8(float* acc, uint4 v, float dv) {
    const __nv_bfloat162* b = reinterpret_cast<const __nv_bfloat162*>(&v);
    #pragma unroll
    for (int q = 0; q < 4; ++q) {
        float2 f = __bfloat1622float2(b[q]);
        acc[2 * q]     = fmaf(dv, f.x, acc[2 * q]);
        acc[2 * q + 1] = fmaf(dv, f.y, acc[2 * q + 1]);
    }
}

// layer 1: yb holds UNscaled bf16(X@W1); apply dinv[src] per gathered row.
__global__ __launch_bounds__(256)
void aggregate1_kernel(const __nv_bfloat16* __restrict__ yb,
                       const float* __restrict__ bias,
                       float* __restrict__ out, int n) {
    int gw   = (blockIdx.x * blockDim.x + threadIdx.x) >> 5;
    int lane = threadIdx.x & 31;
    if (gw >= n) return;
    int e0 = g_rowstart[gw], e1 = g_rowstart[gw + 1];

    float acc[8] = {};

    int e = e0;
    for (; e + 4 <= e1; e += 4) {
        int s0 = g_csr[e], s1 = g_csr[e + 1], s2 = g_csr[e + 2], s3 = g_csr[e + 3];
        float d0 = g_dinv[s0], d1 = g_dinv[s1], d2 = g_dinv[s2], d3 = g_dinv[s3];
        uint4 v0 = ((const uint4*)(yb + (size_t)s0 * DH))[lane];
        uint4 v1 = ((const uint4*)(yb + (size_t)s1 * DH))[lane];
        uint4 v2 = ((const uint4*)(yb + (size_t)s2 * DH))[lane];
        uint4 v3 = ((const uint4*)(yb + (size_t)s3 * DH))[lane];
        acc8(acc, v0, d0); acc8(acc, v1, d1); acc8(acc, v2, d2); acc8(acc, v3, d3);
    }
    for (; e < e1; ++e) {
        int s = g_csr[e];
        uint4 v = ((const uint4*)(yb + (size_t)s * DH))[lane];
        acc8(acc, v, g_dinv[s]);
    }
    float dvn = g_dinv[gw];
    {   // self loop
        uint4 v = ((const uint4*)(yb + (size_t)gw * DH))[lane];
        acc8(acc, v, dvn);
    }
    float4 b0 = ((const float4*)bias)[2 * lane];
    float4 b1 = ((const float4*)bias)[2 * lane + 1];
    float4 r0, r1;
    r0.x = fmaxf(dvn * acc[0] + b0.x, 0.f); r0.y = fmaxf(dvn * acc[1] + b0.y, 0.f);
    r0.z = fmaxf(dvn * acc[2] + b0.z, 0.f); r0.w = fmaxf(dvn * acc[3] + b0.w, 0.f);
    r1.x = fmaxf(dvn * acc[4] + b1.x, 0.f); r1.y = fmaxf(dvn * acc[5] + b1.y, 0.f);
    r1.z = fmaxf(dvn * acc[6] + b1.z, 0.f); r1.w = fmaxf(dvn * acc[7] + b1.w, 0.f);
    float4* op = (float4*)(out + (size_t)gw * DH);
    op[2 * lane]     = r0;
    op[2 * lane + 1] = r1;
}

// layer-2 aggregate fused with pool+FC (yb is pre-scaled by dinv[src] in gemm2 epilogue)
__global__ __launch_bounds__(256)
void aggregate2_pool_kernel(const __nv_bfloat16* __restrict__ yb,
                            const float* __restrict__ bias,
                            const float* __restrict__ wfc,
                            const int* __restrict__ batch, int n) {
    int gw   = (blockIdx.x * blockDim.x + threadIdx.x) >> 5;
    int lane = threadIdx.x & 31;
    if (gw >= n) return;
    int e0 = g_rowstart[gw], e1 = g_rowstart[gw + 1];

    float acc[8] = {};

    int e = e0;
    for (; e + 4 <= e1; e += 4) {
        int s0 = g_csr[e], s1 = g_csr[e + 1], s2 = g_csr[e + 2], s3 = g_csr[e + 3];
        uint4 v0 = ((const uint4*)(yb + (size_t)s0 * DH))[lane];
        uint4 v1 = ((const uint4*)(yb + (size_t)s1 * DH))[lane];
        uint4 v2 = ((const uint4*)(yb + (size_t)s2 * DH))[lane];
        uint4 v3 = ((const uint4*)(yb + (size_t)s3 * DH))[lane];
        acc8(acc, v0, 1.f); acc8(acc, v1, 1.f); acc8(acc, v2, 1.f); acc8(acc, v3, 1.f);
    }
    for (; e < e1; ++e) {
        int s = g_csr[e];
        uint4 v = ((const uint4*)(yb + (size_t)s * DH))[lane];
        acc8(acc, v, 1.f);
    }
    {
        uint4 v = ((const uint4*)(yb + (size_t)gw * DH))[lane];
        acc8(acc, v, 1.f);
    }
    float dv = g_dinv[gw];
    float4 b0 = ((const float4*)bias)[2 * lane];
    float4 b1 = ((const float4*)bias)[2 * lane + 1];
    float4 f0 = ((const float4*)wfc)[2 * lane];
    float4 f1 = ((const float4*)wfc)[2 * lane + 1];

    float h;
    float dot = 0.f;
    h = fmaxf(dv * acc[0] + b0.x, 0.f); dot += h * f0.x;
    h = fmaxf(dv * acc[1] + b0.y, 0.f); dot += h * f0.y;
    h = fmaxf(dv * acc[2] + b0.z, 0.f); dot += h * f0.z;
    h = fmaxf(dv * acc[3] + b0.w, 0.f); dot += h * f0.w;
    h = fmaxf(dv * acc[4] + b1.x, 0.f); dot += h * f1.x;
    h = fmaxf(dv * acc[5] + b1.y, 0.f); dot += h * f1.y;
    h = fmaxf(dv * acc[6] + b1.z, 0.f); dot += h * f1.z;
    h = fmaxf(dv * acc[7] + b1.w, 0.f); dot += h * f1.w;

    #pragma unroll
    for (int off = 16; off > 0; off >>= 1)
        dot += __shfl_xor_sync(0xffffffffu, dot, off);
    if (lane == 0)
        atomicAdd(&g_gsum[batch[gw]], dot);
}

__global__ void finalize_kernel(float* __restrict__ out, const float* __restrict__ bfc) {
    int g = threadIdx.x;
    if (g < NGR)
        out[g] = g_gsum[g] / fmaxf((float)g_cnt[g], 1.0f) + bfc[0];
}

// ---------------- launch ------------------------------------------------------
extern "C" void kernel_launch(void* const* d_in, const int* in_sizes, int n_in,
                              void* d_out, int out_size) {
    const float* x     = (const float*)d_in[0];
    const int*   ei    = (const int*)  d_in[1];
    const int*   batch = (const int*)  d_in[2];
    const float* W1    = (const float*)d_in[3];
    const float* b1    = (const float*)d_in[4];
    const float* W2    = (const float*)d_in[5];
    const float* b2    = (const float*)d_in[6];
    const float* wfc   = (const float*)d_in[7];
    const float* bfc   = (const float*)d_in[8];
    float* out = (float*)d_out;

    int n = in_sizes[0] / DIN;   // 20000
    int e = in_sizes[1] / 2;     // 320000

    __nv_bfloat16* ybptr = nullptr;
    float* hptr = nullptr;
    float* dinvptr = nullptr;
    cudaGetSymbolAddress((void**)&ybptr, g_yb);
    cudaGetSymbolAddress((void**)&hptr, g_h);
    cudaGetSymbolAddress((void**)&dinvptr, g_dinv);

    int gblocks = ((n + BM - 1) / BM) * (DH / BN);   // 157 * 4 = 628

    reset_bar_kernel<<<1, 32>>>();

    hybrid_kernel<<<NCSR + gblocks, 128>>>(x, W1, ybptr, n, ei, batch, e);

    int ta = ((n * 32) + 255) / 256;
    aggregate1_kernel<<<ta, 256>>>(ybptr, b1, hptr, n);

    gemm_kernel<<<gblocks, 128>>>(hptr, W2, dinvptr, ybptr, n, DH);

    aggregate2_pool_kernel<<<ta, 256>>>(ybptr, b2, wfc, batch, n);

    finalize_kernel<<<1, NGR>>>(out, bfc);
}

// round 9
// speedup vs baseline: 1.6153x; 1.1425x over previous
#include <cuda_runtime.h>
#include <cuda_bf16.h>
#include <cuda_fp16.h>
#include <cstdint>

// Problem constants (fixed by dataset)
#define NMAX   20000
#define EMAX   320000
#define DIN    512
#define DH     256
#define NGR    128
#define NCSR   128                     // CSR-builder blocks inside hybrid kernel
#define CSR_THREADS (NCSR * 128)

// ---------------- scratch (static device globals; no runtime alloc) ----------
__device__ int   g_deg[NMAX];
__device__ int   g_rowstart[NMAX + 1];
__device__ int   g_cursor[NMAX];
__device__ int   g_csr[EMAX];
__device__ float g_dinv[NMAX];
__device__ __align__(16) __nv_bfloat16 g_yb[(size_t)NMAX * DH];  // bf16 gather source
__device__ __align__(16) float g_h[(size_t)NMAX * DH];           // layer-1 hidden (fp32)
__device__ float g_gsum[NGR];
__device__ int   g_cnt[NGR];
__device__ int   g_blocksum[NCSR];
__device__ volatile unsigned g_bar[4];

// ---------------- reset (must run before each hybrid launch) ------------------
__global__ void reset_bar_kernel() {
    if (threadIdx.x < 4) g_bar[threadIdx.x] = 0u;
}

// ---------------- spin barrier among the NCSR builder blocks ------------------
__device__ __forceinline__ void csr_barrier(int id) {
    __syncthreads();
    if (threadIdx.x == 0) {
        __threadfence();
        atomicAdd((unsigned*)(g_bar + id), 1u);
        while (g_bar[id] < (unsigned)NCSR) __nanosleep(128);
        __threadfence();
    }
    __syncthreads();
}

// ---------------- CSR build (blocks [0,NCSR) of hybrid kernel; 128 threads) ---
__device__ void csr_build(const int* __restrict__ ei, const int* __restrict__ batch,
                          int n, int e) {
    int tid  = threadIdx.x;                    // 0..127
    int gtid = blockIdx.x * 128 + tid;

    __shared__ int sm[4];
    __shared__ int s_carry;

    // phase 0: zero deg + pooling accumulators
    for (int i = gtid; i < n; i += CSR_THREADS) g_deg[i] = 0;
    if (gtid < NGR) { g_gsum[gtid] = 0.0f; g_cnt[gtid] = 0; }
    if (gtid == 0)  g_rowstart[n] = e;    // sum of in-degrees == e
    csr_barrier(0);

    // phase 1: histogram in-degrees + per-graph node counts
    for (int i = gtid; i < e; i += CSR_THREADS) atomicAdd(&g_deg[ei[e + i]], 1);
    for (int i = gtid; i < n; i += CSR_THREADS) atomicAdd(&g_cnt[batch[i]], 1);
    csr_barrier(1);

    const int chunk = (n + NCSR - 1) / NCSR;   // 157
    int base = blockIdx.x * chunk;
    int lim  = n - base; if (lim > chunk) lim = chunk; if (lim < 0) lim = 0;

    int lane = tid & 31, wid = tid >> 5;       // wid 0..3

    // phase 2a: per-block chunk sum
    int psum = 0;
    for (int i = tid; i < lim; i += 128) psum += __ldcg(&g_deg[base + i]);
    #pragma unroll
    for (int off = 16; off; off >>= 1) psum += __shfl_xor_sync(0xffffffffu, psum, off);
    if (lane == 0) sm[wid] = psum;
    __syncthreads();
    if (tid == 0) g_blocksum[blockIdx.x] = sm[0] + sm[1] + sm[2] + sm[3];
    csr_barrier(2);

    // phase 2b: parallel sum of predecessor blocksums -> this block's offset
    {
        int val = (tid < blockIdx.x) ? __ldcg(&g_blocksum[tid]) : 0;  // tid<128=NCSR
        #pragma unroll
        for (int off = 16; off; off >>= 1) val += __shfl_xor_sync(0xffffffffu, val, off);
        if (lane == 0) sm[wid] = val;
        __syncthreads();
        if (tid == 0) s_carry = sm[0] + sm[1] + sm[2] + sm[3];
        __syncthreads();
    }
    int run = s_carry;
    __syncthreads();

    // phase 2c: exclusive scan of this chunk -> rowstart / cursor / dinv
    for (int o = 0; o < lim; o += 128) {
        int i = base + o + tid;
        int v = (o + tid < lim) ? __ldcg(&g_deg[i]) : 0;
        int x = v;
        #pragma unroll
        for (int off = 1; off < 32; off <<= 1) {
            int t = __shfl_up_sync(0xffffffffu, x, off);
            if (lane >= off) x += t;
        }
        if (lane == 31) sm[wid] = x;
        __syncthreads();
        if (wid == 0 && lane < 4) {
            int s = sm[lane];
            #pragma unroll
            for (int off = 1; off < 4; off <<= 1) {
                int t = __shfl_up_sync(0xfu, s, off);
                if (lane >= off) s += t;
            }
            sm[lane] = s;
        }
        __syncthreads();
        int woff = wid ? sm[wid - 1] : 0;
        if (o + tid < lim) {
            int excl = run + x + woff - v;
            g_rowstart[i] = excl;
            g_cursor[i]   = excl;
            g_dinv[i]     = rsqrtf((float)(v + 1));   // +1 self-loop
        }
        run += sm[3];
        __syncthreads();
    }
    csr_barrier(3);

    // phase 3: scatter edges into CSR
    for (int i = gtid; i < e; i += CSR_THREADS) {
        int s = ei[i];
        int d = ei[e + i];
        int p = atomicAdd(&g_cursor[d], 1);
        g_csr[p] = s;
    }
}

// ---------------- fp16 tensor-core GEMM (m16n8k16, fp32 accum) ----------------
__device__ __forceinline__ uint32_t packh2(float a, float b) {
    __half2 h = __float22half2_rn(make_float2(a, b));
    return *reinterpret_cast<uint32_t*>(&h);
}

__device__ __forceinline__ void mma_f16(float* c, const uint32_t* a, const uint32_t* b) {
    asm volatile(
        "mma.sync.aligned.m16n8k16.row.col.f32.f16.f16.f32 "
        "{%0,%1,%2,%3}, {%4,%5,%6,%7}, {%8,%9}, {%0,%1,%2,%3};\n"
        : "+f"(c[0]), "+f"(c[1]), "+f"(c[2]), "+f"(c[3])
        : "r"(a[0]), "r"(a[1]), "r"(a[2]), "r"(a[3]),
          "r"(b[0]), "r"(b[1]));
}

#define BM 128
#define BN 64
#define BKT 32      // k-values per tile (halves); 16 half2 pairs
#define ASPAD 20    // u32/row: banks 20*gid+tig cover all 32 -> conflict-free a-frags
#define BSPAD 72    // u32/row: 72%32=8 -> 8*tig+gid covers all 32 -> conflict-free b-frags

// Yb[m,:] = bf16( (scale ? scale[m] : 1) * (A[m,:] @ B) )
// 128 threads = 4 warps (2M x 2N), each warp computes 64x32.
// As32[row][kp]: u32 = halves (k=2kp, 2kp+1) of A. Bs32[kp][n]: halves (B[2kp][n], B[2kp+1][n]).
__device__ __forceinline__ void gemm_body(
    const float* __restrict__ A, const float* __restrict__ B,
    const float* __restrict__ scale, __nv_bfloat16* __restrict__ Yb,
    int M, int K, int bid,
    uint32_t (*As)[ASPAD], uint32_t (*Bs)[BSPAD]) {

    int tid  = threadIdx.x;
    int lane = tid & 31, warp = tid >> 5;     // warp 0..3
    int wm = warp >> 1, wn = warp & 1;
    int gid = lane >> 2, tig = lane & 3;
    int m0 = (bid >> 2) * BM;
    int n0 = (bid & 3) * BN;

    float c[4][4][4] = {};
    float4 pa[8];
    float4 pb0[2], pb1[2];

    auto ldA = [&](int k0) {
        #pragma unroll
        for (int t = 0; t < 8; ++t) {
            int f4 = tid + t * 128;
            int r = f4 >> 3, cc = (f4 & 7) << 2;     // cc: k offset (floats)
            int gr = m0 + r;
            pa[t] = (gr < M) ? *(const float4*)(A + (size_t)gr * K + k0 + cc)
                             : make_float4(0.f, 0.f, 0.f, 0.f);
        }
    };
    auto ldB = [&](int k0) {
        #pragma unroll
        for (int t = 0; t < 2; ++t) {
            int slot = tid + t * 128;                // 0..255 uint4 slots
            int kp = slot >> 4;                      // 0..15 k-pair
            int cc = (slot & 15) << 2;               // n offset 0..60
            const float* p0 = B + (size_t)(k0 + 2 * kp)     * DH + n0 + cc;
            const float* p1 = B + (size_t)(k0 + 2 * kp + 1) * DH + n0 + cc;
            pb0[t] = *(const float4*)p0;
            pb1[t] = *(const float4*)p1;
        }
    };
    auto stTile = [&]() {
        #pragma unroll
        for (int t = 0; t < 8; ++t) {
            int f4 = tid + t * 128;
            int r = f4 >> 3, cc = (f4 & 7) << 2;
            uint2 v = make_uint2(packh2(pa[t].x, pa[t].y), packh2(pa[t].z, pa[t].w));
            *(uint2*)&As[r][cc >> 1] = v;
        }
        #pragma unroll
        for (int t = 0; t < 2; ++t) {
            int slot = tid + t * 128;
            int kp = slot >> 4;
            int cc = (slot & 15) << 2;
            uint4 v = make_uint4(packh2(pb0[t].x, pb1[t].x), packh2(pb0[t].y, pb1[t].y),
                                 packh2(pb0[t].z, pb1[t].z), packh2(pb0[t].w, pb1[t].w));
            *(uint4*)&Bs[kp][cc] = v;
        }
    };

    ldA(0); ldB(0); stTile();
    __syncthreads();

    int KT = K / BKT;
    for (int kt = 0; kt < KT; ++kt) {
        if (kt + 1 < KT) { ldA((kt + 1) * BKT); ldB((kt + 1) * BKT); }

        #pragma unroll
        for (int ks = 0; ks < 2; ++ks) {          // two k16 steps per tile
            int kk2 = ks * 8;                      // k-pair offset
            uint32_t a[4][4], b[4][2];
            #pragma unroll
            for (int i = 0; i < 4; ++i) {
                int mrow = wm * 64 + i * 16;
                a[i][0] = As[mrow + gid][kk2 + tig];
                a[i][1] = As[mrow + gid + 8][kk2 + tig];
                a[i][2] = As[mrow + gid][kk2 + tig + 4];
                a[i][3] = As[mrow + gid + 8][kk2 + tig + 4];
            }
            #pragma unroll
            for (int j = 0; j < 4; ++j) {
                int ncol = wn * 32 + j * 8 + gid;
                b[j][0] = Bs[kk2 + tig][ncol];
                b[j][1] = Bs[kk2 + tig + 4][ncol];
            }
            #pragma unroll
            for (int i = 0; i < 4; ++i)
                #pragma unroll
                for (int j = 0; j < 4; ++j)
                    mma_f16(c[i][j], a[i], b[j]);
        }
        __syncthreads();
        if (kt + 1 < KT) { stTile(); __syncthreads(); }
    }

    // epilogue: optional per-row scale, then bf16 pack + store
    #pragma unroll
    for (int i = 0; i < 4; ++i) {
        int r0 = m0 + wm * 64 + i * 16 + gid;
        int r1 = r0 + 8;
        float s0 = 1.f, s1 = 1.f;
        if (scale) {
            s0 = (r0 < M) ? scale[r0] : 0.f;
            s1 = (r1 < M) ? scale[r1] : 0.f;
        }
        #pragma unroll
        for (int j = 0; j < 4; ++j) {
            int cb = n0 + wn * 32 + j * 8 + tig * 2;
            if (r0 < M) {
                __nv_bfloat162 v = __float22bfloat162_rn(
                    make_float2(s0 * c[i][j][0], s0 * c[i][j][1]));
                *(__nv_bfloat162*)(Yb + (size_t)r0 * DH + cb) = v;
            }
            if (r1 < M) {
                __nv_bfloat162 v = __float22bfloat162_rn(
                    make_float2(s1 * c[i][j][2], s1 * c[i][j][3]));
                *(__nv_bfloat162*)(Yb + (size_t)r1 * DH + cb) = v;
            }
        }
    }
}

// hybrid: blocks [0,NCSR) build CSR; the rest compute Yb = bf16(X @ W1) (unscaled)
__global__ __launch_bounds__(128, 2)
void hybrid_kernel(const float* __restrict__ x, const float* __restrict__ W1,
                   __nv_bfloat16* __restrict__ yb, int n,
                   const int* __restrict__ ei, const int* __restrict__ batch, int e) {
    __shared__ __align__(16) uint32_t As[BM][ASPAD];
    __shared__ __align__(16) uint32_t Bs[BKT / 2][BSPAD];
    if (blockIdx.x < NCSR) { csr_build(ei, batch, n, e); return; }
    gemm_body(x, W1, nullptr, yb, n, DIN, blockIdx.x - NCSR, As, Bs);
}

__global__ __launch_bounds__(128, 2)
void gemm_kernel(const float* __restrict__ A, const float* __restrict__ B,
                 const float* __restrict__ scale, __nv_bfloat16* __restrict__ Yb,
                 int M, int K) {
    __shared__ __align__(16) uint32_t As[BM][ASPAD];
    __shared__ __align__(16) uint32_t Bs[BKT / 2][BSPAD];
    gemm_body(A, B, scale, Yb, M, K, blockIdx.x, As, Bs);
}

// ---------------- warp-per-node gather aggregation (bf16 source) --------------
// Each lane owns 8 consecutive channels (one uint4 = 8 bf16 per gathered row).
__device__ __forceinline__ void acc8(float* acc, uint4 v, float dv) {
    const __nv_bfloat162* b = reinterpret_cast<const __nv_bfloat162*>(&v);
    #pragma unroll
    for (int q = 0; q < 4; ++q) {
        float2 f = __bfloat1622float2(b[q]);
        acc[2 * q]     = fmaf(dv, f.x, acc[2 * q]);
        acc[2 * q + 1] = fmaf(dv, f.y, acc[2 * q + 1]);
    }
}

// layer 1: yb holds UNscaled bf16(X@W1); apply dinv[src] per gathered row.
__global__ __launch_bounds__(256)
void aggregate1_kernel(const __nv_bfloat16* __restrict__ yb,
                       const float* __restrict__ bias,
                       float* __restrict__ out, int n) {
    int gw   = (blockIdx.x * blockDim.x + threadIdx.x) >> 5;
    int lane = threadIdx.x & 31;
    if (gw >= n) return;
    int e0 = g_rowstart[gw], e1 = g_rowstart[gw + 1];

    float acc[8] = {};

    int e = e0;
    for (; e + 4 <= e1; e += 4) {
        int s0 = g_csr[e], s1 = g_csr[e + 1], s2 = g_csr[e + 2], s3 = g_csr[e + 3];
        float d0 = g_dinv[s0], d1 = g_dinv[s1], d2 = g_dinv[s2], d3 = g_dinv[s3];
        uint4 v0 = ((const uint4*)(yb + (size_t)s0 * DH))[lane];
        uint4 v1 = ((const uint4*)(yb + (size_t)s1 * DH))[lane];
        uint4 v2 = ((const uint4*)(yb + (size_t)s2 * DH))[lane];
        uint4 v3 = ((const uint4*)(yb + (size_t)s3 * DH))[lane];
        acc8(acc, v0, d0); acc8(acc, v1, d1); acc8(acc, v2, d2); acc8(acc, v3, d3);
    }
    for (; e < e1; ++e) {
        int s = g_csr[e];
        uint4 v = ((const uint4*)(yb + (size_t)s * DH))[lane];
        acc8(acc, v, g_dinv[s]);
    }
    float dvn = g_dinv[gw];
    {   // self loop
        uint4 v = ((const uint4*)(yb + (size_t)gw * DH))[lane];
        acc8(acc, v, dvn);
    }
    float4 b0 = ((const float4*)bias)[2 * lane];
    float4 b1 = ((const float4*)bias)[2 * lane + 1];
    float4 r0, r1;
    r0.x = fmaxf(dvn * acc[0] + b0.x, 0.f); r0.y = fmaxf(dvn * acc[1] + b0.y, 0.f);
    r0.z = fmaxf(dvn * acc[2] + b0.z, 0.f); r0.w = fmaxf(dvn * acc[3] + b0.w, 0.f);
    r1.x = fmaxf(dvn * acc[4] + b1.x, 0.f); r1.y = fmaxf(dvn * acc[5] + b1.y, 0.f);
    r1.z = fmaxf(dvn * acc[6] + b1.z, 0.f); r1.w = fmaxf(dvn * acc[7] + b1.w, 0.f);
    float4* op = (float4*)(out + (size_t)gw * DH);
    op[2 * lane]     = r0;
    op[2 * lane + 1] = r1;
}

// layer-2 aggregate fused with pool+FC (yb is pre-scaled by dinv[src] in gemm2 epilogue)
__global__ __launch_bounds__(256)
void aggregate2_pool_kernel(const __nv_bfloat16* __restrict__ yb,
                            const float* __restrict__ bias,
                            const float* __restrict__ wfc,
                            const int* __restrict__ batch, int n) {
    int gw   = (blockIdx.x * blockDim.x + threadIdx.x) >> 5;
    int lane = threadIdx.x & 31;
    if (gw >= n) return;
    int e0 = g_rowstart[gw], e1 = g_rowstart[gw + 1];

    float acc[8] = {};

    int e = e0;
    for (; e + 4 <= e1; e += 4) {
        int s0 = g_csr[e], s1 = g_csr[e + 1], s2 = g_csr[e + 2], s3 = g_csr[e + 3];
        uint4 v0 = ((const uint4*)(yb + (size_t)s0 * DH))[lane];
        uint4 v1 = ((const uint4*)(yb + (size_t)s1 * DH))[lane];
        uint4 v2 = ((const uint4*)(yb + (size_t)s2 * DH))[lane];
        uint4 v3 = ((const uint4*)(yb + (size_t)s3 * DH))[lane];
        acc8(acc, v0, 1.f); acc8(acc, v1, 1.f); acc8(acc, v2, 1.f); acc8(acc, v3, 1.f);
    }
    for (; e < e1; ++e) {
        int s = g_csr[e];
        uint4 v = ((const uint4*)(yb + (size_t)s * DH))[lane];
        acc8(acc, v, 1.f);
    }
    {
        uint4 v = ((const uint4*)(yb + (size_t)gw * DH))[lane];
        acc8(acc, v, 1.f);
    }
    float dv = g_dinv[gw];
    float4 b0 = ((const float4*)bias)[2 * lane];
    float4 b1 = ((const float4*)bias)[2 * lane + 1];
    float4 f0 = ((const float4*)wfc)[2 * lane];
    float4 f1 = ((const float4*)wfc)[2 * lane + 1];

    float h;
    float dot = 0.f;
    h = fmaxf(dv * acc[0] + b0.x, 0.f); dot += h * f0.x;
    h = fmaxf(dv * acc[1] + b0.y, 0.f); dot += h * f0.y;
    h = fmaxf(dv * acc[2] + b0.z, 0.f); dot += h * f0.z;
    h = fmaxf(dv * acc[3] + b0.w, 0.f); dot += h * f0.w;
    h = fmaxf(dv * acc[4] + b1.x, 0.f); dot += h * f1.x;
    h = fmaxf(dv * acc[5] + b1.y, 0.f); dot += h * f1.y;
    h = fmaxf(dv * acc[6] + b1.z, 0.f); dot += h * f1.z;
    h = fmaxf(dv * acc[7] + b1.w, 0.f); dot += h * f1.w;

    #pragma unroll
    for (int off = 16; off > 0; off >>= 1)
        dot += __shfl_xor_sync(0xffffffffu, dot, off);
    if (lane == 0)
        atomicAdd(&g_gsum[batch[gw]], dot);
}

__global__ void finalize_kernel(float* __restrict__ out, const float* __restrict__ bfc) {
    int g = threadIdx.x;
    if (g < NGR)
        out[g] = g_gsum[g] / fmaxf((float)g_cnt[g], 1.0f) + bfc[0];
}

// ---------------- launch ------------------------------------------------------
extern "C" void kernel_launch(void* const* d_in, const int* in_sizes, int n_in,
                              void* d_out, int out_size) {
    const float* x     = (const float*)d_in[0];
    const int*   ei    = (const int*)  d_in[1];
    const int*   batch = (const int*)  d_in[2];
    const float* W1    = (const float*)d_in[3];
    const float* b1    = (const float*)d_in[4];
    const float* W2    = (const float*)d_in[5];
    const float* b2    = (const float*)d_in[6];
    const float* wfc   = (const float*)d_in[7];
    const float* bfc   = (const float*)d_in[8];
    float* out = (float*)d_out;

    int n = in_sizes[0] / DIN;   // 20000
    int e = in_sizes[1] / 2;     // 320000

    __nv_bfloat16* ybptr = nullptr;
    float* hptr = nullptr;
    float* dinvptr = nullptr;
    cudaGetSymbolAddress((void**)&ybptr, g_yb);
    cudaGetSymbolAddress((void**)&hptr, g_h);
    cudaGetSymbolAddress((void**)&dinvptr, g_dinv);

    int gblocks = ((n + BM - 1) / BM) * (DH / BN);   // 157 * 4 = 628

    reset_bar_kernel<<<1, 32>>>();

    hybrid_kernel<<<NCSR + gblocks, 128>>>(x, W1, ybptr, n, ei, batch, e);

    int ta = ((n * 32) + 255) / 256;
    aggregate1_kernel<<<ta, 256>>>(ybptr, b1, hptr, n);

    gemm_kernel<<<gblocks, 128>>>(hptr, W2, dinvptr, ybptr, n, DH);

    aggregate2_pool_kernel<<<ta, 256>>>(ybptr, b2, wfc, batch, n);

    finalize_kernel<<<1, NGR>>>(out, bfc);
}

// round 10
// speedup vs baseline: 1.8747x; 1.1606x over previous
#include <cuda_runtime.h>
#include <cuda_bf16.h>
#include <cuda_fp16.h>
#include <cstdint>

// Problem constants (fixed by dataset)
#define NMAX   20000
#define EMAX   320000
#define DIN    512
#define DH     256
#define NGR    128
#define NCSR   128                     // CSR-builder blocks inside hybrid kernel
#define CSR_THREADS (NCSR * 128)

// ---------------- scratch (static device globals; no runtime alloc) ----------
__device__ int   g_deg[NMAX];
__device__ int   g_rowstart[NMAX + 1];
__device__ int   g_cursor[NMAX];
__device__ int   g_csr[EMAX];
__device__ float g_dinv[NMAX];
__device__ __align__(16) __nv_bfloat16 g_yb[(size_t)NMAX * DH];  // bf16 gather source
__device__ __align__(16) __half g_h[(size_t)NMAX * DH];          // layer-1 hidden (fp16)
__device__ __align__(16) uint32_t g_w1p[(DIN / 2) * DH];         // W1 packed half2 pairs
__device__ __align__(16) uint32_t g_w2p[(DH / 2) * DH];          // W2 packed half2 pairs
__device__ float g_gsum[NGR];
__device__ int   g_cnt[NGR];
__device__ int   g_blocksum[NCSR];
__device__ volatile unsigned g_bar[4];

// ---------------- helpers -----------------------------------------------------
__device__ __forceinline__ uint32_t packh2(float a, float b) {
    __half2 h = __float22half2_rn(make_float2(a, b));
    return *reinterpret_cast<uint32_t*>(&h);
}

__device__ __forceinline__ void cpa16(uint32_t dst_smem, const void* src, int srcsize) {
    asm volatile("cp.async.cg.shared.global [%0], [%1], 16, %2;\n"
                 :: "r"(dst_smem), "l"(src), "r"(srcsize));
}
#define CP_COMMIT() asm volatile("cp.async.commit_group;\n" ::: "memory")
#define CP_WAIT0()  asm volatile("cp.async.wait_group 0;\n" ::: "memory")

// ---------------- prep: reset barriers + pack W1/W2 into fp16 pair layout -----
__global__ void prep_kernel(const float* __restrict__ W1, const float* __restrict__ W2) {
    int gid = blockIdx.x * blockDim.x + threadIdx.x;
    int nthr = gridDim.x * blockDim.x;
    if (gid < 4) g_bar[gid] = 0u;
    const int t1 = (DIN / 2) * DH;
    for (int i = gid; i < t1; i += nthr) {
        int kp = i / DH, n = i % DH;
        g_w1p[i] = packh2(W1[(2 * kp) * DH + n], W1[(2 * kp + 1) * DH + n]);
    }
    const int t2 = (DH / 2) * DH;
    for (int i = gid; i < t2; i += nthr) {
        int kp = i / DH, n = i % DH;
        g_w2p[i] = packh2(W2[(2 * kp) * DH + n], W2[(2 * kp + 1) * DH + n]);
    }
}

// ---------------- spin barrier among the NCSR builder blocks ------------------
__device__ __forceinline__ void csr_barrier(int id) {
    __syncthreads();
    if (threadIdx.x == 0) {
        __threadfence();
        atomicAdd((unsigned*)(g_bar + id), 1u);
        while (g_bar[id] < (unsigned)NCSR) __nanosleep(128);
        __threadfence();
    }
    __syncthreads();
}

// ---------------- CSR build (blocks [0,NCSR) of hybrid kernel; 128 threads) ---
__device__ void csr_build(const int* __restrict__ ei, const int* __restrict__ batch,
                          int n, int e) {
    int tid  = threadIdx.x;                    // 0..127
    int gtid = blockIdx.x * 128 + tid;

    __shared__ int sm[4];
    __shared__ int s_carry;

    // phase 0: zero deg + pooling accumulators
    for (int i = gtid; i < n; i += CSR_THREADS) g_deg[i] = 0;
    if (gtid < NGR) { g_gsum[gtid] = 0.0f; g_cnt[gtid] = 0; }
    if (gtid == 0)  g_rowstart[n] = e;    // sum of in-degrees == e
    csr_barrier(0);

    // phase 1: histogram in-degrees + per-graph node counts
    for (int i = gtid; i < e; i += CSR_THREADS) atomicAdd(&g_deg[ei[e + i]], 1);
    for (int i = gtid; i < n; i += CSR_THREADS) atomicAdd(&g_cnt[batch[i]], 1);
    csr_barrier(1);

    const int chunk = (n + NCSR - 1) / NCSR;   // 157
    int base = blockIdx.x * chunk;
    int lim  = n - base; if (lim > chunk) lim = chunk; if (lim < 0) lim = 0;

    int lane = tid & 31, wid = tid >> 5;       // wid 0..3

    // phase 2a: per-block chunk sum
    int psum = 0;
    for (int i = tid; i < lim; i += 128) psum += __ldcg(&g_deg[base + i]);
    #pragma unroll
    for (int off = 16; off; off >>= 1) psum += __shfl_xor_sync(0xffffffffu, psum, off);
    if (lane == 0) sm[wid] = psum;
    __syncthreads();
    if (tid == 0) g_blocksum[blockIdx.x] = sm[0] + sm[1] + sm[2] + sm[3];
    csr_barrier(2);

    // phase 2b: parallel sum of predecessor blocksums -> this block's offset
    {
        int val = (tid < blockIdx.x) ? __ldcg(&g_blocksum[tid]) : 0;  // tid<128=NCSR
        #pragma unroll
        for (int off = 16; off; off >>= 1) val += __shfl_xor_sync(0xffffffffu, val, off);
        if (lane == 0) sm[wid] = val;
        __syncthreads();
        if (tid == 0) s_carry = sm[0] + sm[1] + sm[2] + sm[3];
        __syncthreads();
    }
    int run = s_carry;
    __syncthreads();

    // phase 2c: exclusive scan of this chunk -> rowstart / cursor / dinv
    for (int o = 0; o < lim; o += 128) {
        int i = base + o + tid;
        int v = (o + tid < lim) ? __ldcg(&g_deg[i]) : 0;
        int x = v;
        #pragma unroll
        for (int off = 1; off < 32; off <<= 1) {
            int t = __shfl_up_sync(0xffffffffu, x, off);
            if (lane >= off) x += t;
        }
        if (lane == 31) sm[wid] = x;
        __syncthreads();
        if (wid == 0 && lane < 4) {
            int s = sm[lane];
            #pragma unroll
            for (int off = 1; off < 4; off <<= 1) {
                int t = __shfl_up_sync(0xfu, s, off);
                if (lane >= off) s += t;
            }
            sm[lane] = s;
        }
        __syncthreads();
        int woff = wid ? sm[wid - 1] : 0;
        if (o + tid < lim) {
            int excl = run + x + woff - v;
            g_rowstart[i] = excl;
            g_cursor[i]   = excl;
            g_dinv[i]     = rsqrtf((float)(v + 1));   // +1 self-loop
        }
        run += sm[3];
        __syncthreads();
    }
    csr_barrier(3);

    // phase 3: scatter edges into CSR
    for (int i = gtid; i < e; i += CSR_THREADS) {
        int s = ei[i];
        int d = ei[e + i];
        int p = atomicAdd(&g_cursor[d], 1);
        g_csr[p] = s;
    }
}

// ---------------- fp16 tensor-core GEMM (m16n8k16, fp32 accum) ----------------
__device__ __forceinline__ void mma_f16(float* c, const uint32_t* a, const uint32_t* b) {
    asm volatile(
        "mma.sync.aligned.m16n8k16.row.col.f32.f16.f16.f32 "
        "{%0,%1,%2,%3}, {%4,%5,%6,%7}, {%8,%9}, {%0,%1,%2,%3};\n"
        : "+f"(c[0]), "+f"(c[1]), "+f"(c[2]), "+f"(c[3])
        : "r"(a[0]), "r"(a[1]), "r"(a[2]), "r"(a[3]),
          "r"(b[0]), "r"(b[1]));
}

#define BM 128
#define BN 64
#define KPT 16      // k-pairs per tile (= 32 k-values)
#define ASPAD 20    // u32/row: banks 20*gid+tig cover all 32 -> conflict-free a-frags
#define BSPAD 72    // u32/row: 8*tig+gid covers all 32 -> conflict-free b-frags

// Shared memory layout (double-buffered):
//   As[2*BM][ASPAD]  : A tile, row r = u32 k-pairs 0..15 (+pad)
//   Bs[2*KPT][BSPAD] : B tile, row kp = u32 per n column (packed W layout)
// AF16=1: A is fp16 k-pair u32 rows (g_h), loaded via cp.async with zero-fill.
// AF16=0: A is fp32 (x), loaded to regs, packed to fp16, STS'd.
template <int AF16>
__device__ __forceinline__ void gemm_core(
    const float* __restrict__ Af, const uint32_t* __restrict__ Ah,
    const uint32_t* __restrict__ Bp,
    const float* __restrict__ scale, __nv_bfloat16* __restrict__ Yb,
    int M, int K, int bid,
    uint32_t (*As)[ASPAD], uint32_t (*Bs)[BSPAD]) {

    int tid  = threadIdx.x;
    int lane = tid & 31, warp = tid >> 5;     // warp 0..3
    int wm = warp >> 1, wn = warp & 1;
    int gid = lane >> 2, tig = lane & 3;
    int m0 = (bid >> 2) * BM;
    int n0 = (bid & 3) * BN;
    const int KPr = K >> 1;                   // A row stride in u32 (AF16 path)

    uint32_t as_base = (uint32_t)__cvta_generic_to_shared(&As[0][0]);
    uint32_t bs_base = (uint32_t)__cvta_generic_to_shared(&Bs[0][0]);

    float c[4][4][4] = {};
    float4 pa[8];

    auto loadB = [&](int kt, int s) {
        const uint32_t* src = Bp + (size_t)(kt * KPT) * DH + n0;
        #pragma unroll
        for (int t = 0; t < 2; ++t) {
            int cidx = tid + t * 128;
            int kp = cidx >> 4, cc = (cidx & 15) << 2;
            cpa16(bs_base + (((s * KPT + kp) * BSPAD) + cc) * 4, src + kp * DH + cc, 16);
        }
    };
    auto loadA16 = [&](int kt, int s) {
        #pragma unroll
        for (int t = 0; t < 4; ++t) {
            int cidx = tid + t * 128;
            int r = cidx >> 2, cc = (cidx & 3) << 2;
            int gr = m0 + r;
            int sz = (gr < M) ? 16 : 0;
            const uint32_t* src = Ah + (size_t)(gr < M ? gr : 0) * KPr + kt * KPT + cc;
            cpa16(as_base + (((s * BM + r) * ASPAD) + cc) * 4, src, sz);
        }
    };
    auto ldAreg = [&](int kt) {
        #pragma unroll
        for (int t = 0; t < 8; ++t) {
            int f4 = tid + t * 128;
            int r = f4 >> 3, cc = (f4 & 7) << 2;
            int gr = m0 + r;
            pa[t] = (gr < M) ? *(const float4*)(Af + (size_t)gr * K + kt * 32 + cc)
                             : make_float4(0.f, 0.f, 0.f, 0.f);
        }
    };
    auto stA = [&](int s) {
        #pragma unroll
        for (int t = 0; t < 8; ++t) {
            int f4 = tid + t * 128;
            int r = f4 >> 3, cc = (f4 & 7) << 2;
            uint2 v = make_uint2(packh2(pa[t].x, pa[t].y), packh2(pa[t].z, pa[t].w));
            *(uint2*)&As[s * BM + r][cc >> 1] = v;
        }
    };
    auto compute = [&](int s) {
        #pragma unroll
        for (int ks = 0; ks < 2; ++ks) {
            int kk2 = ks * 8;
            uint32_t a[4][4], b[4][2];
            #pragma unroll
            for (int i = 0; i < 4; ++i) {
                int mrow = s * BM + wm * 64 + i * 16;
                a[i][0] = As[mrow + gid][kk2 + tig];
                a[i][1] = As[mrow + gid + 8][kk2 + tig];
                a[i][2] = As[mrow + gid][kk2 + tig + 4];
                a[i][3] = As[mrow + gid + 8][kk2 + tig + 4];
            }
            #pragma unroll
            for (int j = 0; j < 4; ++j) {
                int ncol = wn * 32 + j * 8 + gid;
                b[j][0] = Bs[s * KPT + kk2 + tig][ncol];
                b[j][1] = Bs[s * KPT + kk2 + tig + 4][ncol];
            }
            #pragma unroll
            for (int i = 0; i < 4; ++i)
                #pragma unroll
                for (int j = 0; j < 4; ++j)
                    mma_f16(c[i][j], a[i], b[j]);
        }
    };

    int KT = K / 32;
    // prologue: tile 0 into stage 0
    loadB(0, 0);
    if (AF16) loadA16(0, 0); else ldAreg(0);
    CP_COMMIT();
    if (!AF16) stA(0);
    CP_WAIT0();
    __syncthreads();

    for (int kt = 0; kt < KT; ++kt) {
        int s = kt & 1;
        if (kt + 1 < KT) {
            loadB(kt + 1, s ^ 1);
            if (AF16) loadA16(kt + 1, s ^ 1); else ldAreg(kt + 1);
            CP_COMMIT();
        }
        compute(s);
        if (!AF16 && kt + 1 < KT) stA(s ^ 1);
        if (kt + 1 < KT) { CP_WAIT0(); __syncthreads(); }
    }

    // epilogue: optional per-row scale, then bf16 pack + store
    #pragma unroll
    for (int i = 0; i < 4; ++i) {
        int r0 = m0 + wm * 64 + i * 16 + gid;
        int r1 = r0 + 8;
        float s0 = 1.f, s1 = 1.f;
        if (scale) {
            s0 = (r0 < M) ? scale[r0] : 0.f;
            s1 = (r1 < M) ? scale[r1] : 0.f;
        }
        #pragma unroll
        for (int j = 0; j < 4; ++j) {
            int cb = n0 + wn * 32 + j * 8 + tig * 2;
            if (r0 < M) {
                __nv_bfloat162 v = __float22bfloat162_rn(
                    make_float2(s0 * c[i][j][0], s0 * c[i][j][1]));
                *(__nv_bfloat162*)(Yb + (size_t)r0 * DH + cb) = v;
            }
            if (r1 < M) {
                __nv_bfloat162 v = __float22bfloat162_rn(
                    make_float2(s1 * c[i][j][2], s1 * c[i][j][3]));
                *(__nv_bfloat162*)(Yb + (size_t)r1 * DH + cb) = v;
            }
        }
    }
}

// hybrid: blocks [0,NCSR) build CSR; the rest compute Yb = bf16(X @ W1) (unscaled)
__global__ __launch_bounds__(128, 2)
void hybrid_kernel(const float* __restrict__ x,
                   __nv_bfloat16* __restrict__ yb, int n,
                   const int* __restrict__ ei, const int* __restrict__ batch, int e) {
    __shared__ __align__(16) uint32_t As[2 * BM][ASPAD];
    __shared__ __align__(16) uint32_t Bs[2 * KPT][BSPAD];
    if (blockIdx.x < NCSR) { csr_build(ei, batch, n, e); return; }
    gemm_core<0>(x, nullptr, g_w1p, nullptr, yb, n, DIN, blockIdx.x - NCSR, As, Bs);
}

// gemm2: Yb = bf16( dinv[m] * (h @ W2) ), all-fp16 operands, pure cp.async
__global__ __launch_bounds__(128, 3)
void gemm2_kernel(__nv_bfloat16* __restrict__ Yb, int M) {
    __shared__ __align__(16) uint32_t As[2 * BM][ASPAD];
    __shared__ __align__(16) uint32_t Bs[2 * KPT][BSPAD];
    gemm_core<1>(nullptr, (const uint32_t*)g_h, g_w2p, g_dinv, Yb, M, DH, blockIdx.x, As, Bs);
}

// ---------------- warp-per-node gather aggregation (bf16 source) --------------
// Each lane owns 8 consecutive channels (one uint4 = 8 bf16 per gathered row).
__device__ __forceinline__ void acc8(float* acc, uint4 v, float dv) {
    const __nv_bfloat162* b = reinterpret_cast<const __nv_bfloat162*>(&v);
    #pragma unroll
    for (int q = 0; q < 4; ++q) {
        float2 f = __bfloat1622float2(b[q]);
        acc[2 * q]     = fmaf(dv, f.x, acc[2 * q]);
        acc[2 * q + 1] = fmaf(dv, f.y, acc[2 * q + 1]);
    }
}

// layer 1: yb holds UNscaled bf16(X@W1); apply dinv[src] per gathered row.
// Output h is fp16 (exactly what gemm2 consumes).
__global__ __launch_bounds__(256)
void aggregate1_kernel(const __nv_bfloat16* __restrict__ yb,
                       const float* __restrict__ bias,
                       __half* __restrict__ out, int n) {
    int gw   = (blockIdx.x * blockDim.x + threadIdx.x) >> 5;
    int lane = threadIdx.x & 31;
    if (gw >= n) return;
    int e0 = g_rowstart[gw], e1 = g_rowstart[gw + 1];

    float acc[8] = {};

    int e = e0;
    for (; e + 4 <= e1; e += 4) {
        int s0 = g_csr[e], s1 = g_csr[e + 1], s2 = g_csr[e + 2], s3 = g_csr[e + 3];
        float d0 = g_dinv[s0], d1 = g_dinv[s1], d2 = g_dinv[s2], d3 = g_dinv[s3];
        uint4 v0 = ((const uint4*)(yb + (size_t)s0 * DH))[lane];
        uint4 v1 = ((const uint4*)(yb + (size_t)s1 * DH))[lane];
        uint4 v2 = ((const uint4*)(yb + (size_t)s2 * DH))[lane];
        uint4 v3 = ((const uint4*)(yb + (size_t)s3 * DH))[lane];
        acc8(acc, v0, d0); acc8(acc, v1, d1); acc8(acc, v2, d2); acc8(acc, v3, d3);
    }
    for (; e < e1; ++e) {
        int s = g_csr[e];
        uint4 v = ((const uint4*)(yb + (size_t)s * DH))[lane];
        acc8(acc, v, g_dinv[s]);
    }
    float dvn = g_dinv[gw];
    {   // self loop
        uint4 v = ((const uint4*)(yb + (size_t)gw * DH))[lane];
        acc8(acc, v, dvn);
    }
    float4 b0 = ((const float4*)bias)[2 * lane];
    float4 b1 = ((const float4*)bias)[2 * lane + 1];
    float r[8];
    r[0] = fmaxf(dvn * acc[0] + b0.x, 0.f); r[1] = fmaxf(dvn * acc[1] + b0.y, 0.f);
    r[2] = fmaxf(dvn * acc[2] + b0.z, 0.f); r[3] = fmaxf(dvn * acc[3] + b0.w, 0.f);
    r[4] = fmaxf(dvn * acc[4] + b1.x, 0.f); r[5] = fmaxf(dvn * acc[5] + b1.y, 0.f);
    r[6] = fmaxf(dvn * acc[6] + b1.z, 0.f); r[7] = fmaxf(dvn * acc[7] + b1.w, 0.f);
    uint4 st;
    uint32_t* sp = reinterpret_cast<uint32_t*>(&st);
    sp[0] = packh2(r[0], r[1]); sp[1] = packh2(r[2], r[3]);
    sp[2] = packh2(r[4], r[5]); sp[3] = packh2(r[6], r[7]);
    ((uint4*)(out + (size_t)gw * DH))[lane] = st;
}

// layer-2 aggregate fused with pool+FC (yb is pre-scaled by dinv[src] in gemm2 epilogue)
__global__ __launch_bounds__(256)
void aggregate2_pool_kernel(const __nv_bfloat16* __restrict__ yb,
                            const float* __restrict__ bias,
                            const float* __restrict__ wfc,
                            const int* __restrict__ batch, int n) {
    int gw   = (blockIdx.x * blockDim.x + threadIdx.x) >> 5;
    int lane = threadIdx.x & 31;
    if (gw >= n) return;
    int e0 = g_rowstart[gw], e1 = g_rowstart[gw + 1];

    float acc[8] = {};

    int e = e0;
    for (; e + 4 <= e1; e += 4) {
        int s0 = g_csr[e], s1 = g_csr[e + 1], s2 = g_csr[e + 2], s3 = g_csr[e + 3];
        uint4 v0 = ((const uint4*)(yb + (size_t)s0 * DH))[lane];
        uint4 v1 = ((const uint4*)(yb + (size_t)s1 * DH))[lane];
        uint4 v2 = ((const uint4*)(yb + (size_t)s2 * DH))[lane];
        uint4 v3 = ((const uint4*)(yb + (size_t)s3 * DH))[lane];
        acc8(acc, v0, 1.f); acc8(acc, v1, 1.f); acc8(acc, v2, 1.f); acc8(acc, v3, 1.f);
    }
    for (; e < e1; ++e) {
        int s = g_csr[e];
        uint4 v = ((const uint4*)(yb + (size_t)s * DH))[lane];
        acc8(acc, v, 1.f);
    }
    {
        uint4 v = ((const uint4*)(yb + (size_t)gw * DH))[lane];
        acc8(acc, v, 1.f);
    }
    float dv = g_dinv[gw];
    float4 b0 = ((const float4*)bias)[2 * lane];
    float4 b1 = ((const float4*)bias)[2 * lane + 1];
    float4 f0 = ((const float4*)wfc)[2 * lane];
    float4 f1 = ((const float4*)wfc)[2 * lane + 1];

    float h;
    float dot = 0.f;
    h = fmaxf(dv * acc[0] + b0.x, 0.f); dot += h * f0.x;
    h = fmaxf(dv * acc[1] + b0.y, 0.f); dot += h * f0.y;
    h = fmaxf(dv * acc[2] + b0.z, 0.f); dot += h * f0.z;
    h = fmaxf(dv * acc[3] + b0.w, 0.f); dot += h * f0.w;
    h = fmaxf(dv * acc[4] + b1.x, 0.f); dot += h * f1.x;
    h = fmaxf(dv * acc[5] + b1.y, 0.f); dot += h * f1.y;
    h = fmaxf(dv * acc[6] + b1.z, 0.f); dot += h * f1.z;
    h = fmaxf(dv * acc[7] + b1.w, 0.f); dot += h * f1.w;

    #pragma unroll
    for (int off = 16; off > 0; off >>= 1)
        dot += __shfl_xor_sync(0xffffffffu, dot, off);
    if (lane == 0)
        atomicAdd(&g_gsum[batch[gw]], dot);
}

__global__ void finalize_kernel(float* __restrict__ out, const float* __restrict__ bfc) {
    int g = threadIdx.x;
    if (g < NGR)
        out[g] = g_gsum[g] / fmaxf((float)g_cnt[g], 1.0f) + bfc[0];
}

// ---------------- launch ------------------------------------------------------
extern "C" void kernel_launch(void* const* d_in, const int* in_sizes, int n_in,
                              void* d_out, int out_size) {
    const float* x     = (const float*)d_in[0];
    const int*   ei    = (const int*)  d_in[1];
    const int*   batch = (const int*)  d_in[2];
    const float* W1    = (const float*)d_in[3];
    const float* b1    = (const float*)d_in[4];
    const float* W2    = (const float*)d_in[5];
    const float* b2    = (const float*)d_in[6];
    const float* wfc   = (const float*)d_in[7];
    const float* bfc   = (const float*)d_in[8];
    float* out = (float*)d_out;

    int n = in_sizes[0] / DIN;   // 20000
    int e = in_sizes[1] / 2;     // 320000

    __nv_bfloat16* ybptr = nullptr;
    __half* hptr = nullptr;
    cudaGetSymbolAddress((void**)&ybptr, g_yb);
    cudaGetSymbolAddress((void**)&hptr, g_h);

    int gblocks = ((n + BM - 1) / BM) * (DH / BN);   // 157 * 4 = 628

    prep_kernel<<<192, 256>>>(W1, W2);

    hybrid_kernel<<<NCSR + gblocks, 128>>>(x, ybptr, n, ei, batch, e);

    int ta = ((n * 32) + 255) / 256;
    aggregate1_kernel<<<ta, 256>>>(ybptr, b1, hptr, n);

    gemm2_kernel<<<gblocks, 128>>>(ybptr, n);

    aggregate2_pool_kernel<<<ta, 256>>>(ybptr, b2, wfc, batch, n);

    finalize_kernel<<<1, NGR>>>(out, bfc);
}